// round 1
// baseline (speedup 1.0000x reference)
#include <cuda_runtime.h>
#include <cuda_bf16.h>
#include <math.h>

// ---------------------------------------------------------------------------
// DeepSeek V2 decoder layer, S=2048, D=2048, H=16, QL=1536, KVL=512,
// DN=128, DR=64, DV=128, I=8192.  All fp32.
// ---------------------------------------------------------------------------

#define S_  2048
#define D_  2048
#define H_  16
#define QL_ 1536
#define KVL_ 512
#define DN_ 128
#define DR_ 64
#define DV_ 128
#define I_  8192
#define EPS_ 1e-6f
#define SCALE_ 0.07216878364870323f   // (DN+DR)^-0.5 = 192^-0.5

// ---- scratch layout (single __device__ global, offsets in floats) ----------
#define OFF_H        0L
#define OFF_QA       (OFF_H       + (long)S_*D_)          // 4,194,304
#define OFF_Q        (OFF_QA      + (long)S_*QL_)         // +3,145,728
#define OFF_KV       (OFF_Q       + (long)S_*H_*(DN_+DR_))// +6,291,456
#define OFF_KF       (OFF_KV      + (long)S_*(KVL_+DR_))  // +1,179,648
#define OFF_QF       (OFF_KF      + (long)S_*(KVL_+DR_))  // +1,179,648
#define OFF_SCORES   (OFF_QF      + (long)H_*S_*(KVL_+DR_)) // +18,874,368
#define OFF_OLAT     (OFF_SCORES  + (long)H_*S_*S_)       // +67,108,864
#define OFF_O        (OFF_OLAT    + (long)H_*S_*KVL_)     // +16,777,216
#define OFF_HID2     (OFF_O       + (long)S_*D_)          // +4,194,304
#define OFF_X2       (OFF_HID2    + (long)S_*D_)          // +4,194,304
#define OFF_GU       (OFF_X2      + (long)S_*D_)          // +4,194,304
#define OFF_ACT      (OFF_GU      + (long)S_*2*I_)        // +33,554,432
#define SCRATCH_TOTAL (OFF_ACT    + (long)S_*I_)          // +16,777,216

__device__ __align__(256) float g_scratch[SCRATCH_TOTAL];

// ---------------------------------------------------------------------------
// block reductions
// ---------------------------------------------------------------------------
__device__ __forceinline__ float blockReduceSum(float v) {
    __shared__ float red[32];
    int lane = threadIdx.x & 31, w = threadIdx.x >> 5;
    #pragma unroll
    for (int o = 16; o; o >>= 1) v += __shfl_xor_sync(0xffffffffu, v, o);
    if (lane == 0) red[w] = v;
    __syncthreads();
    if (w == 0) {
        float x = (lane < (int)(blockDim.x >> 5)) ? red[lane] : 0.f;
        #pragma unroll
        for (int o = 16; o; o >>= 1) x += __shfl_xor_sync(0xffffffffu, x, o);
        if (lane == 0) red[0] = x;
    }
    __syncthreads();
    float r = red[0];
    __syncthreads();
    return r;
}

__device__ __forceinline__ float blockReduceMax(float v) {
    __shared__ float red[32];
    int lane = threadIdx.x & 31, w = threadIdx.x >> 5;
    #pragma unroll
    for (int o = 16; o; o >>= 1) v = fmaxf(v, __shfl_xor_sync(0xffffffffu, v, o));
    if (lane == 0) red[w] = v;
    __syncthreads();
    if (w == 0) {
        float x = (lane < (int)(blockDim.x >> 5)) ? red[lane] : -3.4e38f;
        #pragma unroll
        for (int o = 16; o; o >>= 1) x = fmaxf(x, __shfl_xor_sync(0xffffffffu, x, o));
        if (lane == 0) red[0] = x;
    }
    __syncthreads();
    float r = red[0];
    __syncthreads();
    return r;
}

// ---------------------------------------------------------------------------
// rmsnorm: one block per row
// ---------------------------------------------------------------------------
__global__ void rmsnorm_kernel(const float* __restrict__ x,
                               const float* __restrict__ w,
                               float* __restrict__ out, int N) {
    long row = blockIdx.x;
    const float* xr = x + row * N;
    float* orow = out + row * N;
    float ss = 0.f;
    for (int i = threadIdx.x; i < N; i += blockDim.x) { float v = xr[i]; ss += v * v; }
    ss = blockReduceSum(ss);
    float inv = rsqrtf(ss / (float)N + EPS_);
    for (int i = threadIdx.x; i < N; i += blockDim.x) orow[i] = xr[i] * inv * w[i];
}

// ---------------------------------------------------------------------------
// k preparation: rmsnorm of kv[:, :512] -> kf[:, :512]; rope of kv[:,512:576]
// -> kf[:, 512:576].  one block per sequence position.
// ---------------------------------------------------------------------------
__global__ void kprep_kernel(const float* __restrict__ kv,
                             const float* __restrict__ w,
                             const float* __restrict__ cosT,
                             const float* __restrict__ sinT,
                             float* __restrict__ kf) {
    long s = blockIdx.x;
    const float* row = kv + s * (KVL_ + DR_);
    float* krow = kf + s * (KVL_ + DR_);
    float ss = 0.f;
    for (int i = threadIdx.x; i < KVL_; i += blockDim.x) { float v = row[i]; ss += v * v; }
    ss = blockReduceSum(ss);
    float inv = rsqrtf(ss / (float)KVL_ + EPS_);
    for (int i = threadIdx.x; i < KVL_; i += blockDim.x) krow[i] = row[i] * inv * w[i];
    int i = threadIdx.x;
    if (i < DR_) {
        float x = row[KVL_ + i];
        float rot = (i < DR_ / 2) ? -row[KVL_ + i + DR_ / 2] : row[KVL_ + i - DR_ / 2];
        krow[KVL_ + i] = x * cosT[s * DR_ + i] + rot * sinT[s * DR_ + i];
    }
}

// ---------------------------------------------------------------------------
// q_pe rope into qf[h][s][512:576]. grid (S, H), 64 threads
// ---------------------------------------------------------------------------
__global__ void qrope_kernel(const float* __restrict__ q,
                             const float* __restrict__ cosT,
                             const float* __restrict__ sinT,
                             float* __restrict__ qf) {
    long s = blockIdx.x;
    int h = blockIdx.y;
    int i = threadIdx.x;
    const float* qp = q + s * (long)(H_ * (DN_ + DR_)) + h * (DN_ + DR_) + DN_;
    float x = qp[i];
    float rot = (i < DR_ / 2) ? -qp[i + DR_ / 2] : qp[i - DR_ / 2];
    qf[((long)h * S_ + s) * (KVL_ + DR_) + KVL_ + i] =
        x * cosT[s * DR_ + i] + rot * sinT[s * DR_ + i];
}

// ---------------------------------------------------------------------------
// causal softmax in-place on scores[h][s][t]; zero masked tail.
// grid (S, H), 256 threads
// ---------------------------------------------------------------------------
__global__ void softmax_causal_kernel(float* __restrict__ scores) {
    long s = blockIdx.x;
    int h = blockIdx.y;
    float* row = scores + ((long)h * S_ + s) * S_;
    int L = (int)s + 1;
    float m = -3.4e38f;
    for (int i = threadIdx.x; i < L; i += blockDim.x) m = fmaxf(m, row[i]);
    m = blockReduceMax(m);
    float sum = 0.f;
    for (int i = threadIdx.x; i < L; i += blockDim.x) {
        float e = __expf(row[i] - m);
        row[i] = e;
        sum += e;
    }
    sum = blockReduceSum(sum);
    float inv = 1.f / sum;
    for (int i = threadIdx.x; i < L; i += blockDim.x) row[i] *= inv;
    for (int i = L + threadIdx.x; i < S_; i += blockDim.x) row[i] = 0.f;
}

// ---------------------------------------------------------------------------
// swiglu: act = silu(gu[:, :I]) * gu[:, I:]
// ---------------------------------------------------------------------------
__global__ void swiglu_kernel(const float* __restrict__ gu, float* __restrict__ act) {
    long idx = (long)blockIdx.x * blockDim.x + threadIdx.x;
    if (idx >= (long)S_ * I_) return;
    long s = idx / I_, i = idx % I_;
    float g = gu[s * (2L * I_) + i];
    float u = gu[s * (2L * I_) + I_ + i];
    float si = g / (1.f + __expf(-g));
    act[idx] = si * u;
}

// ---------------------------------------------------------------------------
// generic batched SGEMM: C = alpha * A * op(B) (+ add), 128x128x8 tiles,
// 256 threads, 8x8 microtile. TB=true means B accessed as [n][k] (B^T).
// ---------------------------------------------------------------------------
#define BM 128
#define BN 128
#define BK 8
#define TM 8
#define TN 8

template <bool TB>
__global__ void __launch_bounds__(256)
gemm_kernel(const float* __restrict__ A, int lda, long sA,
            const float* __restrict__ B, int ldb, long sB,
            float* __restrict__ C, int ldc, long sC,
            int M, int N, int K, float alpha,
            const float* __restrict__ add, int ldad, long sAd) {
    int bz = blockIdx.z;
    A += (long)bz * sA;
    B += (long)bz * sB;
    C += (long)bz * sC;
    if (add) add += (long)bz * sAd;

    int m0 = blockIdx.y * BM;
    int n0 = blockIdx.x * BN;

    __shared__ float As[BK][BM];
    __shared__ float Bs[BK][BN];

    int tid = threadIdx.x;
    int tx = tid & 15, ty = tid >> 4;

    float acc[TM][TN];
    #pragma unroll
    for (int i = 0; i < TM; i++)
        #pragma unroll
        for (int j = 0; j < TN; j++) acc[i][j] = 0.f;

    for (int k0 = 0; k0 < K; k0 += BK) {
        // A tile: 128 x 8
        #pragma unroll
        for (int i = 0; i < 4; i++) {
            int idx = tid + i * 256;
            int m = idx >> 3, k = idx & 7;
            float v = 0.f;
            if (m0 + m < M && k0 + k < K) v = A[(long)(m0 + m) * lda + k0 + k];
            As[k][m] = v;
        }
        // B tile: 8 x 128
        #pragma unroll
        for (int i = 0; i < 4; i++) {
            int idx = tid + i * 256;
            int k, n;
            if (TB) { n = idx >> 3; k = idx & 7; }
            else    { k = idx >> 7; n = idx & 127; }
            float v = 0.f;
            if (n0 + n < N && k0 + k < K)
                v = TB ? B[(long)(n0 + n) * ldb + k0 + k]
                       : B[(long)(k0 + k) * ldb + n0 + n];
            Bs[k][n] = v;
        }
        __syncthreads();
        #pragma unroll
        for (int k = 0; k < BK; k++) {
            float a[TM], b[TN];
            #pragma unroll
            for (int i = 0; i < TM; i++) a[i] = As[k][ty * TM + i];
            #pragma unroll
            for (int j = 0; j < TN; j++) b[j] = Bs[k][tx * TN + j];
            #pragma unroll
            for (int i = 0; i < TM; i++)
                #pragma unroll
                for (int j = 0; j < TN; j++) acc[i][j] += a[i] * b[j];
        }
        __syncthreads();
    }

    #pragma unroll
    for (int i = 0; i < TM; i++) {
        int m = m0 + ty * TM + i;
        if (m >= M) continue;
        #pragma unroll
        for (int j = 0; j < TN; j++) {
            int n = n0 + tx * TN + j;
            if (n >= N) continue;
            float v = alpha * acc[i][j];
            if (add) v += add[(long)m * ldad + n];
            C[(long)m * ldc + n] = v;
        }
    }
}

// ---------------------------------------------------------------------------
// host-side launcher helpers
// ---------------------------------------------------------------------------
static inline void launch_gemm(bool tb,
                               const float* A, int lda, long sA,
                               const float* B, int ldb, long sB,
                               float* C, int ldc, long sC,
                               int M, int N, int K, float alpha,
                               const float* add, int ldad, long sAd, int batch) {
    dim3 grid((N + BN - 1) / BN, (M + BM - 1) / BM, batch);
    if (tb)
        gemm_kernel<true><<<grid, 256>>>(A, lda, sA, B, ldb, sB, C, ldc, sC,
                                         M, N, K, alpha, add, ldad, sAd);
    else
        gemm_kernel<false><<<grid, 256>>>(A, lda, sA, B, ldb, sB, C, ldc, sC,
                                          M, N, K, alpha, add, ldad, sAd);
}

extern "C" void kernel_launch(void* const* d_in, const int* in_sizes, int n_in,
                              void* d_out, int out_size) {
    const float* hidden   = (const float*)d_in[0];   // (1,S,D)
    const float* cosT     = (const float*)d_in[1];   // (S,DR)
    const float* sinT     = (const float*)d_in[2];   // (S,DR)
    const float* ln1_w    = (const float*)d_in[3];   // (D)
    const float* q_a_w    = (const float*)d_in[4];   // (D,QL)
    const float* q_a_ln_w = (const float*)d_in[5];   // (QL)
    const float* q_b_w    = (const float*)d_in[6];   // (QL, H*(DN+DR))
    const float* kv_a_w   = (const float*)d_in[7];   // (D, KVL+DR)
    const float* kv_a_ln_w= (const float*)d_in[8];   // (KVL)
    const float* kc_w     = (const float*)d_in[9];   // (H,DN,KVL)
    const float* vc_w     = (const float*)d_in[10];  // (H,KVL,DV)
    const float* o_w      = (const float*)d_in[11];  // (H*DV, D)
    const float* ln2_w    = (const float*)d_in[12];  // (D)
    const float* gate_up_w= (const float*)d_in[13];  // (D, 2I)
    const float* down_w   = (const float*)d_in[14];  // (I, D)
    float* out            = (float*)d_out;           // (1,S,D)

    float* sc = nullptr;
    cudaGetSymbolAddress((void**)&sc, g_scratch);

    float* h_     = sc + OFF_H;
    float* qa     = sc + OFF_QA;
    float* q      = sc + OFF_Q;
    float* kv     = sc + OFF_KV;
    float* kf     = sc + OFF_KF;
    float* qf     = sc + OFF_QF;
    float* scores = sc + OFF_SCORES;
    float* olat   = sc + OFF_OLAT;
    float* o      = sc + OFF_O;
    float* hid2   = sc + OFF_HID2;
    float* x2     = sc + OFF_X2;
    float* gu     = sc + OFF_GU;
    float* act    = sc + OFF_ACT;

    const int DF = DN_ + DR_;      // 192
    const int CF = KVL_ + DR_;     // 576

    // 1. h = rmsnorm(hidden, ln1_w)
    rmsnorm_kernel<<<S_, 256>>>(hidden, ln1_w, h_, D_);

    // 2. qa = h @ q_a_w          [S,QL]
    launch_gemm(false, h_, D_, 0, q_a_w, QL_, 0, qa, QL_, 0,
                S_, QL_, D_, 1.f, nullptr, 0, 0, 1);

    // 3. qa = rmsnorm(qa, q_a_ln_w) in-place
    rmsnorm_kernel<<<S_, 256>>>(qa, q_a_ln_w, qa, QL_);

    // 4. q = qa @ q_b_w          [S, H*192]
    launch_gemm(false, qa, QL_, 0, q_b_w, H_ * DF, 0, q, H_ * DF, 0,
                S_, H_ * DF, QL_, 1.f, nullptr, 0, 0, 1);

    // 5. kv = h @ kv_a_w         [S, 576]
    launch_gemm(false, h_, D_, 0, kv_a_w, CF, 0, kv, CF, 0,
                S_, CF, D_, 1.f, nullptr, 0, 0, 1);

    // 6. kf = [rmsnorm(kv[:, :512]), rope(kv[:, 512:])]
    kprep_kernel<<<S_, 256>>>(kv, kv_a_ln_w, cosT, sinT, kf);

    // 7. qf[h][:, :512] = q_nope[h] @ kc_w[h]  (batched over heads)
    launch_gemm(false,
                q, H_ * DF, (long)DF,                 // A: q_nope of head h (col offset h*192)
                kc_w, KVL_, (long)DN_ * KVL_,          // B: kc_w[h] [128,512]
                qf, CF, (long)S_ * CF,                 // C: qf[h][:, :512]
                S_, KVL_, DN_, 1.f, nullptr, 0, 0, H_);

    // 8. qf[h][:, 512:576] = rope(q_pe)
    qrope_kernel<<<dim3(S_, H_), DR_>>>(q, cosT, sinT, qf);

    // 9. scores[h] = SCALE * qf[h] @ kf^T      [S,S] per head
    launch_gemm(true,
                qf, CF, (long)S_ * CF,
                kf, CF, 0,
                scores, S_, (long)S_ * S_,
                S_, S_, CF, SCALE_, nullptr, 0, 0, H_);

    // 10. causal softmax in-place (zeros masked tail)
    softmax_causal_kernel<<<dim3(S_, H_), 256>>>(scores);

    // 11. olat[h] = attn[h] @ k_lat   (k_lat = kf[:, :512], ld 576)
    launch_gemm(false,
                scores, S_, (long)S_ * S_,
                kf, CF, 0,
                olat, KVL_, (long)S_ * KVL_,
                S_, KVL_, S_, 1.f, nullptr, 0, 0, H_);

    // 12. o[:, h*128:(h+1)*128] = olat[h] @ vc_w[h]
    launch_gemm(false,
                olat, KVL_, (long)S_ * KVL_,
                vc_w, DV_, (long)KVL_ * DV_,
                o, H_ * DV_, (long)DV_,
                S_, DV_, KVL_, 1.f, nullptr, 0, 0, H_);

    // 13. hid2 = o @ o_w + hidden (residual)
    launch_gemm(false, o, H_ * DV_, 0, o_w, D_, 0, hid2, D_, 0,
                S_, D_, H_ * DV_, 1.f, hidden, D_, 0, 1);

    // 14. x2 = rmsnorm(hid2, ln2_w)
    rmsnorm_kernel<<<S_, 256>>>(hid2, ln2_w, x2, D_);

    // 15. gu = x2 @ gate_up_w    [S, 2I]
    launch_gemm(false, x2, D_, 0, gate_up_w, 2 * I_, 0, gu, 2 * I_, 0,
                S_, 2 * I_, D_, 1.f, nullptr, 0, 0, 1);

    // 16. act = silu(gu[:, :I]) * gu[:, I:]
    {
        long total = (long)S_ * I_;
        int blocks = (int)((total + 255) / 256);
        swiglu_kernel<<<blocks, 256>>>(gu, act);
    }

    // 17. out = act @ down_w + hid2
    launch_gemm(false, act, I_, 0, down_w, D_, 0, out, D_, 0,
                S_, D_, I_, 1.f, hid2, D_, 0, 1);
}

// round 2
// speedup vs baseline: 1.2628x; 1.2628x over previous
#include <cuda_runtime.h>
#include <cuda_bf16.h>
#include <math.h>

// ---------------------------------------------------------------------------
// DeepSeek V2 decoder layer, S=2048, D=2048, H=16, QL=1536, KVL=512,
// DN=128, DR=64, DV=128, I=8192.  All fp32.
// ---------------------------------------------------------------------------

#define S_  2048
#define D_  2048
#define H_  16
#define QL_ 1536
#define KVL_ 512
#define DN_ 128
#define DR_ 64
#define DV_ 128
#define I_  8192
#define EPS_ 1e-6f
#define SCALE_ 0.07216878364870323f   // (DN+DR)^-0.5 = 192^-0.5

// ---- scratch layout (single __device__ global, offsets in floats) ----------
#define OFF_H        0L
#define OFF_QA       (OFF_H       + (long)S_*D_)
#define OFF_Q        (OFF_QA      + (long)S_*QL_)
#define OFF_KV       (OFF_Q       + (long)S_*H_*(DN_+DR_))
#define OFF_KF       (OFF_KV      + (long)S_*(KVL_+DR_))
#define OFF_QF       (OFF_KF      + (long)S_*(KVL_+DR_))
#define OFF_SCORES   (OFF_QF      + (long)H_*S_*(KVL_+DR_))
#define OFF_OLAT     (OFF_SCORES  + (long)H_*S_*S_)
#define OFF_O        (OFF_OLAT    + (long)H_*S_*KVL_)
#define OFF_HID2     (OFF_O       + (long)S_*D_)
#define OFF_X2       (OFF_HID2    + (long)S_*D_)
#define OFF_GU       (OFF_X2      + (long)S_*D_)
#define OFF_ACT      (OFF_GU      + (long)S_*2*I_)
#define SCRATCH_TOTAL (OFF_ACT    + (long)S_*I_)

__device__ __align__(256) float g_scratch[SCRATCH_TOTAL];

// ---------------------------------------------------------------------------
// block reductions
// ---------------------------------------------------------------------------
__device__ __forceinline__ float blockReduceSum(float v) {
    __shared__ float red[32];
    int lane = threadIdx.x & 31, w = threadIdx.x >> 5;
    #pragma unroll
    for (int o = 16; o; o >>= 1) v += __shfl_xor_sync(0xffffffffu, v, o);
    if (lane == 0) red[w] = v;
    __syncthreads();
    if (w == 0) {
        float x = (lane < (int)(blockDim.x >> 5)) ? red[lane] : 0.f;
        #pragma unroll
        for (int o = 16; o; o >>= 1) x += __shfl_xor_sync(0xffffffffu, x, o);
        if (lane == 0) red[0] = x;
    }
    __syncthreads();
    float r = red[0];
    __syncthreads();
    return r;
}

__device__ __forceinline__ float blockReduceMax(float v) {
    __shared__ float red[32];
    int lane = threadIdx.x & 31, w = threadIdx.x >> 5;
    #pragma unroll
    for (int o = 16; o; o >>= 1) v = fmaxf(v, __shfl_xor_sync(0xffffffffu, v, o));
    if (lane == 0) red[w] = v;
    __syncthreads();
    if (w == 0) {
        float x = (lane < (int)(blockDim.x >> 5)) ? red[lane] : -3.4e38f;
        #pragma unroll
        for (int o = 16; o; o >>= 1) x = fmaxf(x, __shfl_xor_sync(0xffffffffu, x, o));
        if (lane == 0) red[0] = x;
    }
    __syncthreads();
    float r = red[0];
    __syncthreads();
    return r;
}

// ---------------------------------------------------------------------------
// rmsnorm: one block per row
// ---------------------------------------------------------------------------
__global__ void rmsnorm_kernel(const float* __restrict__ x,
                               const float* __restrict__ w,
                               float* __restrict__ out, int N) {
    long row = blockIdx.x;
    const float* xr = x + row * N;
    float* orow = out + row * N;
    float ss = 0.f;
    for (int i = threadIdx.x; i < N; i += blockDim.x) { float v = xr[i]; ss += v * v; }
    ss = blockReduceSum(ss);
    float inv = rsqrtf(ss / (float)N + EPS_);
    for (int i = threadIdx.x; i < N; i += blockDim.x) orow[i] = xr[i] * inv * w[i];
}

// ---------------------------------------------------------------------------
// k preparation
// ---------------------------------------------------------------------------
__global__ void kprep_kernel(const float* __restrict__ kv,
                             const float* __restrict__ w,
                             const float* __restrict__ cosT,
                             const float* __restrict__ sinT,
                             float* __restrict__ kf) {
    long s = blockIdx.x;
    const float* row = kv + s * (KVL_ + DR_);
    float* krow = kf + s * (KVL_ + DR_);
    float ss = 0.f;
    for (int i = threadIdx.x; i < KVL_; i += blockDim.x) { float v = row[i]; ss += v * v; }
    ss = blockReduceSum(ss);
    float inv = rsqrtf(ss / (float)KVL_ + EPS_);
    for (int i = threadIdx.x; i < KVL_; i += blockDim.x) krow[i] = row[i] * inv * w[i];
    int i = threadIdx.x;
    if (i < DR_) {
        float x = row[KVL_ + i];
        float rot = (i < DR_ / 2) ? -row[KVL_ + i + DR_ / 2] : row[KVL_ + i - DR_ / 2];
        krow[KVL_ + i] = x * cosT[s * DR_ + i] + rot * sinT[s * DR_ + i];
    }
}

// ---------------------------------------------------------------------------
// q_pe rope into qf[h][s][512:576]. grid (S, H), 64 threads
// ---------------------------------------------------------------------------
__global__ void qrope_kernel(const float* __restrict__ q,
                             const float* __restrict__ cosT,
                             const float* __restrict__ sinT,
                             float* __restrict__ qf) {
    long s = blockIdx.x;
    int h = blockIdx.y;
    int i = threadIdx.x;
    const float* qp = q + s * (long)(H_ * (DN_ + DR_)) + h * (DN_ + DR_) + DN_;
    float x = qp[i];
    float rot = (i < DR_ / 2) ? -qp[i + DR_ / 2] : qp[i - DR_ / 2];
    qf[((long)h * S_ + s) * (KVL_ + DR_) + KVL_ + i] =
        x * cosT[s * DR_ + i] + rot * sinT[s * DR_ + i];
}

// ---------------------------------------------------------------------------
// causal softmax in-place on scores[h][s][t]; zero masked tail.
// ---------------------------------------------------------------------------
__global__ void softmax_causal_kernel(float* __restrict__ scores) {
    long s = blockIdx.x;
    int h = blockIdx.y;
    float* row = scores + ((long)h * S_ + s) * S_;
    int L = (int)s + 1;
    float m = -3.4e38f;
    for (int i = threadIdx.x; i < L; i += blockDim.x) m = fmaxf(m, row[i]);
    m = blockReduceMax(m);
    float sum = 0.f;
    for (int i = threadIdx.x; i < L; i += blockDim.x) {
        float e = __expf(row[i] - m);
        row[i] = e;
        sum += e;
    }
    sum = blockReduceSum(sum);
    float inv = 1.f / sum;
    for (int i = threadIdx.x; i < L; i += blockDim.x) row[i] *= inv;
    for (int i = L + threadIdx.x; i < S_; i += blockDim.x) row[i] = 0.f;
}

// ---------------------------------------------------------------------------
// swiglu
// ---------------------------------------------------------------------------
__global__ void swiglu_kernel(const float* __restrict__ gu, float* __restrict__ act) {
    long idx = (long)blockIdx.x * blockDim.x + threadIdx.x;
    if (idx >= (long)S_ * I_) return;
    long s = idx / I_, i = idx % I_;
    float g = gu[s * (2L * I_) + i];
    float u = gu[s * (2L * I_) + I_ + i];
    float si = g / (1.f + __expf(-g));
    act[idx] = si * u;
}

// ---------------------------------------------------------------------------
// Batched SGEMM, 128x128x16 tiles, 256 threads, 8x8 microtile, double-buffered
// shared memory, fully vectorized loads. C = alpha*A*op(B) (+ add).
// TB=true: B accessed as [n][k] (B^T).
// ---------------------------------------------------------------------------
#define BM 128
#define BN 128
#define BK 16
#define BMp (BM + 4)
#define BNp (BN + 4)

#define SETCOMP(vec, j, val)                       \
    do {                                           \
        if ((j) == 0) (vec).x = (val);             \
        else if ((j) == 1) (vec).y = (val);        \
        else if ((j) == 2) (vec).z = (val);        \
        else (vec).w = (val);                      \
    } while (0)

#define GETCOMP(vec, j) ((j) == 0 ? (vec).x : (j) == 1 ? (vec).y : (j) == 2 ? (vec).z : (vec).w)

template <bool TB>
__global__ void __launch_bounds__(256, 2)
gemm_kernel(const float* __restrict__ A, int lda, long sA,
            const float* __restrict__ B, int ldb, long sB,
            float* __restrict__ C, int ldc, long sC,
            int M, int N, int K, float alpha,
            const float* __restrict__ add, int ldad, long sAd) {
    __shared__ float As[2][BK][BMp];
    __shared__ float Bs[2][BK][BNp];

    int bz = blockIdx.z;
    A += (long)bz * sA;
    B += (long)bz * sB;
    C += (long)bz * sC;
    if (add) add += (long)bz * sAd;

    const int m0 = blockIdx.y * BM;
    const int n0 = blockIdx.x * BN;
    const int tid = threadIdx.x;
    const int tx = tid & 15, ty = tid >> 4;

    const bool vecA = (m0 + BM <= M);
    const bool vecB = (n0 + BN <= N);

    float4 pa[2], pb[2];

    float acc[8][8];
    #pragma unroll
    for (int i = 0; i < 8; i++)
        #pragma unroll
        for (int j = 0; j < 8; j++) acc[i][j] = 0.f;

    const int nk = K / BK;   // all K are multiples of 16 in this layer

    // ---- fetch tile k0 into registers ----
    auto fetchA = [&](int k0) {
        if (vecA) {
            #pragma unroll
            for (int i = 0; i < 2; i++) {
                int v = tid + i * 256;
                int row = v >> 2, kb = (v & 3) * 4;
                pa[i] = *(const float4*)(A + (long)(m0 + row) * lda + k0 + kb);
            }
        } else {
            #pragma unroll
            for (int i = 0; i < 2; i++) {
                #pragma unroll
                for (int j = 0; j < 4; j++) {
                    int idx = tid + (i * 4 + j) * 256;
                    int row = idx >> 4, k = idx & 15;
                    float v = (m0 + row < M) ? A[(long)(m0 + row) * lda + k0 + k] : 0.f;
                    SETCOMP(pa[i], j, v);
                }
            }
        }
    };
    auto fetchB = [&](int k0) {
        if (!TB) {
            if (vecB) {
                #pragma unroll
                for (int i = 0; i < 2; i++) {
                    int v = tid + i * 256;
                    int kr = v >> 5, c = (v & 31) * 4;
                    pb[i] = *(const float4*)(B + (long)(k0 + kr) * ldb + n0 + c);
                }
            } else {
                #pragma unroll
                for (int i = 0; i < 2; i++) {
                    #pragma unroll
                    for (int j = 0; j < 4; j++) {
                        int idx = tid + (i * 4 + j) * 256;
                        int kr = idx >> 7, n = idx & 127;
                        float v = (n0 + n < N) ? B[(long)(k0 + kr) * ldb + n0 + n] : 0.f;
                        SETCOMP(pb[i], j, v);
                    }
                }
            }
        } else {
            if (vecB) {
                #pragma unroll
                for (int i = 0; i < 2; i++) {
                    int v = tid + i * 256;
                    int row = v >> 2, kb = (v & 3) * 4;
                    pb[i] = *(const float4*)(B + (long)(n0 + row) * ldb + k0 + kb);
                }
            } else {
                #pragma unroll
                for (int i = 0; i < 2; i++) {
                    #pragma unroll
                    for (int j = 0; j < 4; j++) {
                        int idx = tid + (i * 4 + j) * 256;
                        int row = idx >> 4, k = idx & 15;
                        float v = (n0 + row < N) ? B[(long)(n0 + row) * ldb + k0 + k] : 0.f;
                        SETCOMP(pb[i], j, v);
                    }
                }
            }
        }
    };
    // ---- store register tile into shared stage st ----
    auto storeA = [&](int st) {
        if (vecA) {
            #pragma unroll
            for (int i = 0; i < 2; i++) {
                int v = tid + i * 256;
                int row = v >> 2, kb = (v & 3) * 4;
                As[st][kb + 0][row] = pa[i].x;
                As[st][kb + 1][row] = pa[i].y;
                As[st][kb + 2][row] = pa[i].z;
                As[st][kb + 3][row] = pa[i].w;
            }
        } else {
            #pragma unroll
            for (int i = 0; i < 2; i++) {
                #pragma unroll
                for (int j = 0; j < 4; j++) {
                    int idx = tid + (i * 4 + j) * 256;
                    int row = idx >> 4, k = idx & 15;
                    As[st][k][row] = GETCOMP(pa[i], j);
                }
            }
        }
    };
    auto storeB = [&](int st) {
        if (!TB) {
            if (vecB) {
                #pragma unroll
                for (int i = 0; i < 2; i++) {
                    int v = tid + i * 256;
                    int kr = v >> 5, c = (v & 31) * 4;
                    *(float4*)&Bs[st][kr][c] = pb[i];
                }
            } else {
                #pragma unroll
                for (int i = 0; i < 2; i++) {
                    #pragma unroll
                    for (int j = 0; j < 4; j++) {
                        int idx = tid + (i * 4 + j) * 256;
                        int kr = idx >> 7, n = idx & 127;
                        Bs[st][kr][n] = GETCOMP(pb[i], j);
                    }
                }
            }
        } else {
            if (vecB) {
                #pragma unroll
                for (int i = 0; i < 2; i++) {
                    int v = tid + i * 256;
                    int row = v >> 2, kb = (v & 3) * 4;
                    Bs[st][kb + 0][row] = pb[i].x;
                    Bs[st][kb + 1][row] = pb[i].y;
                    Bs[st][kb + 2][row] = pb[i].z;
                    Bs[st][kb + 3][row] = pb[i].w;
                }
            } else {
                #pragma unroll
                for (int i = 0; i < 2; i++) {
                    #pragma unroll
                    for (int j = 0; j < 4; j++) {
                        int idx = tid + (i * 4 + j) * 256;
                        int row = idx >> 4, k = idx & 15;
                        Bs[st][k][row] = GETCOMP(pb[i], j);
                    }
                }
            }
        }
    };

    // prologue: tile 0
    fetchA(0); fetchB(0);
    storeA(0); storeB(0);
    __syncthreads();

    for (int t = 0; t < nk; t++) {
        int cur = t & 1;
        if (t + 1 < nk) { fetchA((t + 1) * BK); fetchB((t + 1) * BK); }

        #pragma unroll
        for (int kk = 0; kk < BK; kk++) {
            float4 a0 = *(const float4*)&As[cur][kk][ty * 8];
            float4 a1 = *(const float4*)&As[cur][kk][ty * 8 + 4];
            float4 b0 = *(const float4*)&Bs[cur][kk][tx * 8];
            float4 b1 = *(const float4*)&Bs[cur][kk][tx * 8 + 4];
            float a[8] = {a0.x, a0.y, a0.z, a0.w, a1.x, a1.y, a1.z, a1.w};
            float b[8] = {b0.x, b0.y, b0.z, b0.w, b1.x, b1.y, b1.z, b1.w};
            #pragma unroll
            for (int i = 0; i < 8; i++)
                #pragma unroll
                for (int j = 0; j < 8; j++) acc[i][j] += a[i] * b[j];
        }

        if (t + 1 < nk) { storeA(cur ^ 1); storeB(cur ^ 1); }
        __syncthreads();
    }

    // epilogue
    if (vecA && vecB) {
        #pragma unroll
        for (int i = 0; i < 8; i++) {
            long m = m0 + ty * 8 + i;
            #pragma unroll
            for (int jj = 0; jj < 2; jj++) {
                int n = n0 + tx * 8 + jj * 4;
                float4 v;
                v.x = alpha * acc[i][jj * 4 + 0];
                v.y = alpha * acc[i][jj * 4 + 1];
                v.z = alpha * acc[i][jj * 4 + 2];
                v.w = alpha * acc[i][jj * 4 + 3];
                if (add) {
                    float4 r = *(const float4*)&add[m * ldad + n];
                    v.x += r.x; v.y += r.y; v.z += r.z; v.w += r.w;
                }
                *(float4*)&C[m * ldc + n] = v;
            }
        }
    } else {
        #pragma unroll
        for (int i = 0; i < 8; i++) {
            int m = m0 + ty * 8 + i;
            if (m >= M) continue;
            #pragma unroll
            for (int j = 0; j < 8; j++) {
                int n = n0 + tx * 8 + j;
                if (n >= N) continue;
                float v = alpha * acc[i][j];
                if (add) v += add[(long)m * ldad + n];
                C[(long)m * ldc + n] = v;
            }
        }
    }
}

// ---------------------------------------------------------------------------
// host-side launcher helpers
// ---------------------------------------------------------------------------
static inline void launch_gemm(bool tb,
                               const float* A, int lda, long sA,
                               const float* B, int ldb, long sB,
                               float* C, int ldc, long sC,
                               int M, int N, int K, float alpha,
                               const float* add, int ldad, long sAd, int batch) {
    dim3 grid((N + BN - 1) / BN, (M + BM - 1) / BM, batch);
    if (tb)
        gemm_kernel<true><<<grid, 256>>>(A, lda, sA, B, ldb, sB, C, ldc, sC,
                                         M, N, K, alpha, add, ldad, sAd);
    else
        gemm_kernel<false><<<grid, 256>>>(A, lda, sA, B, ldb, sB, C, ldc, sC,
                                          M, N, K, alpha, add, ldad, sAd);
}

extern "C" void kernel_launch(void* const* d_in, const int* in_sizes, int n_in,
                              void* d_out, int out_size) {
    const float* hidden   = (const float*)d_in[0];   // (1,S,D)
    const float* cosT     = (const float*)d_in[1];   // (S,DR)
    const float* sinT     = (const float*)d_in[2];   // (S,DR)
    const float* ln1_w    = (const float*)d_in[3];   // (D)
    const float* q_a_w    = (const float*)d_in[4];   // (D,QL)
    const float* q_a_ln_w = (const float*)d_in[5];   // (QL)
    const float* q_b_w    = (const float*)d_in[6];   // (QL, H*(DN+DR))
    const float* kv_a_w   = (const float*)d_in[7];   // (D, KVL+DR)
    const float* kv_a_ln_w= (const float*)d_in[8];   // (KVL)
    const float* kc_w     = (const float*)d_in[9];   // (H,DN,KVL)
    const float* vc_w     = (const float*)d_in[10];  // (H,KVL,DV)
    const float* o_w      = (const float*)d_in[11];  // (H*DV, D)
    const float* ln2_w    = (const float*)d_in[12];  // (D)
    const float* gate_up_w= (const float*)d_in[13];  // (D, 2I)
    const float* down_w   = (const float*)d_in[14];  // (I, D)
    float* out            = (float*)d_out;           // (1,S,D)

    float* sc = nullptr;
    cudaGetSymbolAddress((void**)&sc, g_scratch);

    float* h_     = sc + OFF_H;
    float* qa     = sc + OFF_QA;
    float* q      = sc + OFF_Q;
    float* kv     = sc + OFF_KV;
    float* kf     = sc + OFF_KF;
    float* qf     = sc + OFF_QF;
    float* scores = sc + OFF_SCORES;
    float* olat   = sc + OFF_OLAT;
    float* o      = sc + OFF_O;
    float* hid2   = sc + OFF_HID2;
    float* x2     = sc + OFF_X2;
    float* gu     = sc + OFF_GU;
    float* act    = sc + OFF_ACT;

    const int DF = DN_ + DR_;      // 192
    const int CF = KVL_ + DR_;     // 576

    // 1. h = rmsnorm(hidden, ln1_w)
    rmsnorm_kernel<<<S_, 256>>>(hidden, ln1_w, h_, D_);

    // 2. qa = h @ q_a_w          [S,QL]
    launch_gemm(false, h_, D_, 0, q_a_w, QL_, 0, qa, QL_, 0,
                S_, QL_, D_, 1.f, nullptr, 0, 0, 1);

    // 3. qa = rmsnorm(qa, q_a_ln_w) in-place
    rmsnorm_kernel<<<S_, 256>>>(qa, q_a_ln_w, qa, QL_);

    // 4. q = qa @ q_b_w          [S, H*192]
    launch_gemm(false, qa, QL_, 0, q_b_w, H_ * DF, 0, q, H_ * DF, 0,
                S_, H_ * DF, QL_, 1.f, nullptr, 0, 0, 1);

    // 5. kv = h @ kv_a_w         [S, 576]
    launch_gemm(false, h_, D_, 0, kv_a_w, CF, 0, kv, CF, 0,
                S_, CF, D_, 1.f, nullptr, 0, 0, 1);

    // 6. kf = [rmsnorm(kv[:, :512]), rope(kv[:, 512:])]
    kprep_kernel<<<S_, 256>>>(kv, kv_a_ln_w, cosT, sinT, kf);

    // 7. qf[h][:, :512] = q_nope[h] @ kc_w[h]  (batched over heads)
    launch_gemm(false,
                q, H_ * DF, (long)DF,
                kc_w, KVL_, (long)DN_ * KVL_,
                qf, CF, (long)S_ * CF,
                S_, KVL_, DN_, 1.f, nullptr, 0, 0, H_);

    // 8. qf[h][:, 512:576] = rope(q_pe)
    qrope_kernel<<<dim3(S_, H_), DR_>>>(q, cosT, sinT, qf);

    // 9. scores[h] = SCALE * qf[h] @ kf^T      [S,S] per head
    launch_gemm(true,
                qf, CF, (long)S_ * CF,
                kf, CF, 0,
                scores, S_, (long)S_ * S_,
                S_, S_, CF, SCALE_, nullptr, 0, 0, H_);

    // 10. causal softmax in-place (zeros masked tail)
    softmax_causal_kernel<<<dim3(S_, H_), 256>>>(scores);

    // 11. olat[h] = attn[h] @ k_lat   (k_lat = kf[:, :512], ld 576)
    launch_gemm(false,
                scores, S_, (long)S_ * S_,
                kf, CF, 0,
                olat, KVL_, (long)S_ * KVL_,
                S_, KVL_, S_, 1.f, nullptr, 0, 0, H_);

    // 12. o[:, h*128:(h+1)*128] = olat[h] @ vc_w[h]
    launch_gemm(false,
                olat, KVL_, (long)S_ * KVL_,
                vc_w, DV_, (long)KVL_ * DV_,
                o, H_ * DV_, (long)DV_,
                S_, DV_, KVL_, 1.f, nullptr, 0, 0, H_);

    // 13. hid2 = o @ o_w + hidden (residual)
    launch_gemm(false, o, H_ * DV_, 0, o_w, D_, 0, hid2, D_, 0,
                S_, D_, H_ * DV_, 1.f, hidden, D_, 0, 1);

    // 14. x2 = rmsnorm(hid2, ln2_w)
    rmsnorm_kernel<<<S_, 256>>>(hid2, ln2_w, x2, D_);

    // 15. gu = x2 @ gate_up_w    [S, 2I]
    launch_gemm(false, x2, D_, 0, gate_up_w, 2 * I_, 0, gu, 2 * I_, 0,
                S_, 2 * I_, D_, 1.f, nullptr, 0, 0, 1);

    // 16. act = silu(gu[:, :I]) * gu[:, I:]
    {
        long total = (long)S_ * I_;
        int blocks = (int)((total + 255) / 256);
        swiglu_kernel<<<blocks, 256>>>(gu, act);
    }

    // 17. out = act @ down_w + hid2
    launch_gemm(false, act, I_, 0, down_w, D_, 0, out, D_, 0,
                S_, D_, I_, 1.f, hid2, D_, 0, 1);
}

// round 4
// speedup vs baseline: 3.1526x; 2.4965x over previous
#include <cuda_runtime.h>
#include <cuda_bf16.h>
#include <cstdint>
#include <math.h>

// ---------------------------------------------------------------------------
// DeepSeek V2 decoder layer via mma.sync HMMA (bf16 hi/lo split, fp32 acc).
// S=2048, D=2048, H=16, QL=1536, KVL=512, DN=128, DR=64, DV=128, I=8192.
// ---------------------------------------------------------------------------

#define S_  2048
#define D_  2048
#define H_  16
#define QL_ 1536
#define KVL_ 512
#define DN_ 128
#define DR_ 64
#define DV_ 128
#define I_  8192
#define EPS_ 1e-6f
#define SCALE_ 0.07216878364870323f   // 192^-0.5
#define CF_ 576
#define DF_ 192

// ------------------------- fp32 scratch -------------------------------------
#define OFF_H        0L
#define OFF_QA       (OFF_H       + (long)S_*D_)
#define OFF_Q        (OFF_QA      + (long)S_*QL_)
#define OFF_KV       (OFF_Q       + (long)S_*H_*DF_)
#define OFF_KF       (OFF_KV      + (long)S_*CF_)
#define OFF_QF       (OFF_KF      + (long)S_*CF_)
#define OFF_SCORES   (OFF_QF      + (long)H_*S_*CF_)
#define OFF_OLAT     (OFF_SCORES  + (long)H_*S_*S_)
#define OFF_O        (OFF_OLAT    + (long)H_*S_*KVL_)
#define OFF_HID2     (OFF_O       + (long)S_*D_)
#define OFF_X2       (OFF_HID2    + (long)S_*D_)
#define OFF_GU       (OFF_X2      + (long)S_*D_)
#define OFF_ACT      (OFF_GU      + (long)S_*2*I_)
#define SCRATCH_TOTAL (OFF_ACT    + (long)S_*I_)

__device__ __align__(256) float g_scratch[SCRATCH_TOTAL];

// ------------------------- bf16 scratch (hi at OFF, lo at OFF+E) ------------
#define E_HS    ((long)S_*D_)
#define E_QAS   ((long)S_*QL_)
#define E_QS    ((long)S_*H_*DF_)
#define E_QFS   ((long)H_*S_*CF_)
#define E_KFS   ((long)S_*CF_)
#define E_KFT   ((long)CF_*S_)
#define E_ATT   ((long)H_*S_*S_)
#define E_OLS   ((long)H_*S_*KVL_)
#define E_OS    ((long)S_*D_)
#define E_X2S   ((long)S_*D_)
#define E_ACTS  ((long)S_*I_)
#define E_WQA   ((long)D_*QL_)
#define E_WQB   ((long)QL_*H_*DF_)
#define E_WKVA  ((long)D_*CF_)
#define E_WKC   ((long)H_*DN_*KVL_)
#define E_WVC   ((long)H_*KVL_*DV_)
#define E_WO    ((long)D_*D_)
#define E_WGU   ((long)D_*2*I_)
#define E_WDN   ((long)I_*D_)

#define B_HS    0L
#define B_QAS   (B_HS   + 2*E_HS)
#define B_QS    (B_QAS  + 2*E_QAS)
#define B_QFS   (B_QS   + 2*E_QS)
#define B_KFS   (B_QFS  + 2*E_QFS)
#define B_KFT   (B_KFS  + 2*E_KFS)
#define B_ATT   (B_KFT  + 2*E_KFT)
#define B_OLS   (B_ATT  + 2*E_ATT)
#define B_OS    (B_OLS  + 2*E_OLS)
#define B_X2S   (B_OS   + 2*E_OS)
#define B_ACTS  (B_X2S  + 2*E_X2S)
#define B_WQA   (B_ACTS + 2*E_ACTS)
#define B_WQB   (B_WQA  + 2*E_WQA)
#define B_WKVA  (B_WQB  + 2*E_WQB)
#define B_WKC   (B_WKVA + 2*E_WKVA)
#define B_WVC   (B_WKC  + 2*E_WKC)
#define B_WO    (B_WVC  + 2*E_WVC)
#define B_WGU   (B_WO   + 2*E_WO)
#define B_WDN   (B_WGU  + 2*E_WGU)
#define BF_TOTAL (B_WDN + 2*E_WDN)

__device__ __align__(256) __nv_bfloat16 g_bf[BF_TOTAL];

// ---------------------------------------------------------------------------
// low-level helpers (all base-target instructions: sm_80+)
// ---------------------------------------------------------------------------
__device__ __forceinline__ uint32_t smem_u32(const void* p) {
    uint32_t a;
    asm("{ .reg .u64 t; cvta.to.shared.u64 t, %1; cvt.u32.u64 %0, t; }"
        : "=r"(a) : "l"(p));
    return a;
}

__device__ __forceinline__ void ldmat_x4(uint32_t* r, uint32_t addr) {
    asm volatile("ldmatrix.sync.aligned.m8n8.x4.shared.b16 {%0,%1,%2,%3}, [%4];"
                 : "=r"(r[0]), "=r"(r[1]), "=r"(r[2]), "=r"(r[3]) : "r"(addr));
}

__device__ __forceinline__ void mma16816(float* c, const uint32_t* a, const uint32_t* b) {
    asm volatile(
        "mma.sync.aligned.m16n8k16.row.col.f32.bf16.bf16.f32 "
        "{%0,%1,%2,%3}, {%4,%5,%6,%7}, {%8,%9}, {%0,%1,%2,%3};"
        : "+f"(c[0]), "+f"(c[1]), "+f"(c[2]), "+f"(c[3])
        : "r"(a[0]), "r"(a[1]), "r"(a[2]), "r"(a[3]), "r"(b[0]), "r"(b[1]));
}

__device__ __forceinline__ void cp_async16(uint32_t saddr, const void* gptr) {
    asm volatile("cp.async.cg.shared.global [%0], [%1], 16;"
                 :: "r"(saddr), "l"(__cvta_generic_to_global(gptr)));
}
#define CP_COMMIT() asm volatile("cp.async.commit_group;" ::: "memory")
#define CP_WAIT(n)  asm volatile("cp.async.wait_group %0;" :: "n"(n) : "memory")

// ---------------------------------------------------------------------------
// GEMM: C[M,N] = alpha * sum_k A[m,k]*B[n,k] (+ add)
// A bf16 hi/lo row-major [M][lda]; B bf16 hi/lo row-major [N][ldb] (K contig).
// 128x128x32 tile, 256 thr, 8 warps of 64x32, mma.sync m16n8k16 bf16, 3-pass.
// causal: 0 none, 1 skip n0 > m0+127, 2 K limited to m0+128.
// ---------------------------------------------------------------------------
#define BKc   32
#define ROWB  80                       // padded smem row: 32 bf16 + 16B pad
#define TILE_B (128 * ROWB)            // 10240
#define STAGE_B (4 * TILE_B)           // 40960: Ahi, Alo, Bhi, Blo
#define GEMM_SMEM (2 * STAGE_B)        // 81920

__global__ void __launch_bounds__(256, 1)
gemm_tc(const __nv_bfloat16* __restrict__ Ahi, const __nv_bfloat16* __restrict__ Alo,
        int lda, long sA,
        const __nv_bfloat16* __restrict__ Bhi, const __nv_bfloat16* __restrict__ Blo,
        int ldb, long sB,
        float* __restrict__ C, int ldc, long sC,
        int M, int N, int K, float alpha,
        const float* __restrict__ add, int ldad, long sAd,
        int causal) {
    const int m0 = blockIdx.y * 128;
    const int n0 = blockIdx.x * 128;
    if (causal == 1 && n0 > m0 + 127) return;

    const int bz = blockIdx.z;
    Ahi += (long)bz * sA;  Alo += (long)bz * sA;
    Bhi += (long)bz * sB;  Blo += (long)bz * sB;
    C   += (long)bz * sC;
    if (add) add += (long)bz * sAd;

    const int kmax = (causal == 2) ? min(K, m0 + 128) : K;
    const int nk = kmax / BKc;

    extern __shared__ __align__(128) char smem[];
    const uint32_t sbase = smem_u32(smem);
    const int tid = threadIdx.x, lane = tid & 31, wid = tid >> 5;
    const int wm = wid & 1, wn = wid >> 1;     // warp tile: rows wm*64, cols wn*32

    float acc[4][4][4];
    #pragma unroll
    for (int i = 0; i < 4; i++)
        #pragma unroll
        for (int j = 0; j < 4; j++)
            #pragma unroll
            for (int r = 0; r < 4; r++) acc[i][j][r] = 0.f;

    auto load_stage = [&](int t) {
        const int k0 = t * BKc;
        const uint32_t sb = sbase + (t & 1) * STAGE_B;
        #pragma unroll
        for (int i = 0; i < 8; i++) {
            int idx = tid + i * 256;
            int tb = idx >> 9, r = (idx >> 2) & 127, ch = idx & 3;
            uint32_t sa = sb + tb * TILE_B + r * ROWB + ch * 16;
            if (tb == 0) {
                cp_async16(sa, Ahi + (long)(m0 + r) * lda + k0 + ch * 8);
            } else if (tb == 1) {
                cp_async16(sa, Alo + (long)(m0 + r) * lda + k0 + ch * 8);
            } else {
                const __nv_bfloat16* g = (tb == 2 ? Bhi : Blo);
                if (n0 + r < N) {
                    cp_async16(sa, g + (long)(n0 + r) * ldb + k0 + ch * 8);
                } else {
                    asm volatile("st.shared.v4.b32 [%0], {%1,%1,%1,%1};"
                                 :: "r"(sa), "r"(0) : "memory");
                }
            }
        }
        CP_COMMIT();
    };

    load_stage(0);
    for (int t = 0; t < nk; t++) {
        if (t + 1 < nk) { load_stage(t + 1); CP_WAIT(1); }
        else            { CP_WAIT(0); }
        __syncthreads();

        const uint32_t sb = sbase + (t & 1) * STAGE_B;
        #pragma unroll
        for (int kk = 0; kk < 2; kk++) {
            uint32_t ah[4][4], al[4][4];
            uint32_t bh[4][2], bl[4][2];
            // A fragments: 4 m-tiles of 16 rows
            #pragma unroll
            for (int mi = 0; mi < 4; mi++) {
                int row = wm * 64 + mi * 16 + (lane & 15);
                uint32_t a = sb + row * ROWB + kk * 32 + ((lane >> 4) & 1) * 16;
                ldmat_x4(ah[mi], a);
                ldmat_x4(al[mi], a + TILE_B);
            }
            // B fragments: 2 ldmatrix per precision, each covers 2 n-tiles
            #pragma unroll
            for (int nb = 0; nb < 2; nb++) {
                int row = wn * 32 + nb * 16 + ((lane >> 4) & 1) * 8 + (lane & 7);
                uint32_t a = sb + 2 * TILE_B + row * ROWB + kk * 32 + ((lane >> 3) & 1) * 16;
                uint32_t rh[4], rl[4];
                ldmat_x4(rh, a);
                ldmat_x4(rl, a + TILE_B);
                bh[2 * nb][0] = rh[0]; bh[2 * nb][1] = rh[1];
                bh[2 * nb + 1][0] = rh[2]; bh[2 * nb + 1][1] = rh[3];
                bl[2 * nb][0] = rl[0]; bl[2 * nb][1] = rl[1];
                bl[2 * nb + 1][0] = rl[2]; bl[2 * nb + 1][1] = rl[3];
            }
            #pragma unroll
            for (int mi = 0; mi < 4; mi++)
                #pragma unroll
                for (int ni = 0; ni < 4; ni++) {
                    mma16816(acc[mi][ni], ah[mi], bh[ni]);
                    mma16816(acc[mi][ni], ah[mi], bl[ni]);
                    mma16816(acc[mi][ni], al[mi], bh[ni]);
                }
        }
        __syncthreads();
    }

    // epilogue: acc (mi,ni): c0,c1 -> (row, col..col+1); c2,c3 -> (row+8, ...)
    #pragma unroll
    for (int mi = 0; mi < 4; mi++) {
        #pragma unroll
        for (int ni = 0; ni < 4; ni++) {
            long row = m0 + wm * 64 + mi * 16 + (lane >> 2);
            int col = n0 + wn * 32 + ni * 8 + (lane & 3) * 2;
            if (col < N) {
                float2 v0, v1;
                v0.x = alpha * acc[mi][ni][0];
                v0.y = alpha * acc[mi][ni][1];
                v1.x = alpha * acc[mi][ni][2];
                v1.y = alpha * acc[mi][ni][3];
                if (add) {
                    float2 r0 = *(const float2*)&add[row * ldad + col];
                    float2 r1 = *(const float2*)&add[(row + 8) * ldad + col];
                    v0.x += r0.x; v0.y += r0.y;
                    v1.x += r1.x; v1.y += r1.y;
                }
                *(float2*)&C[row * ldc + col] = v0;
                *(float2*)&C[(row + 8) * ldc + col] = v1;
            }
        }
    }
}

// ---------------------------------------------------------------------------
// split kernels: fp32 -> bf16 hi + bf16 lo
// ---------------------------------------------------------------------------
__global__ void split_rm(const float* __restrict__ x,
                         __nv_bfloat16* __restrict__ hi,
                         __nv_bfloat16* __restrict__ lo, long n4) {
    long i = (long)blockIdx.x * blockDim.x + threadIdx.x;
    if (i >= n4) return;
    float4 v = ((const float4*)x)[i];
    __nv_bfloat16 h0 = __float2bfloat16(v.x), h1 = __float2bfloat16(v.y);
    __nv_bfloat16 h2 = __float2bfloat16(v.z), h3 = __float2bfloat16(v.w);
    __nv_bfloat162* hp = (__nv_bfloat162*)hi;
    __nv_bfloat162* lp = (__nv_bfloat162*)lo;
    hp[i * 2 + 0] = __nv_bfloat162(h0, h1);
    hp[i * 2 + 1] = __nv_bfloat162(h2, h3);
    lp[i * 2 + 0] = __nv_bfloat162(__float2bfloat16(v.x - __bfloat162float(h0)),
                                   __float2bfloat16(v.y - __bfloat162float(h1)));
    lp[i * 2 + 1] = __nv_bfloat162(__float2bfloat16(v.z - __bfloat162float(h2)),
                                   __float2bfloat16(v.w - __bfloat162float(h3)));
}

// transpose-split: x [R][C] fp32 -> hi/lo [C][R] bf16
__global__ void tsplit_kernel(const float* __restrict__ x,
                              __nv_bfloat16* __restrict__ hi,
                              __nv_bfloat16* __restrict__ lo,
                              int R, int C, long sIn, long sOut) {
    __shared__ float tile[32][33];
    int b = blockIdx.z;
    x += (long)b * sIn; hi += (long)b * sOut; lo += (long)b * sOut;
    int c0 = blockIdx.x * 32, r0 = blockIdx.y * 32;
    int tx = threadIdx.x, ty = threadIdx.y;
    #pragma unroll
    for (int j = 0; j < 32; j += 8) {
        int r = r0 + ty + j, c = c0 + tx;
        tile[ty + j][tx] = (r < R && c < C) ? x[(long)r * C + c] : 0.f;
    }
    __syncthreads();
    #pragma unroll
    for (int j = 0; j < 32; j += 8) {
        int c = c0 + ty + j, r = r0 + tx;
        if (c < C && r < R) {
            float v = tile[tx][ty + j];
            __nv_bfloat16 h = __float2bfloat16(v);
            hi[(long)c * R + r] = h;
            lo[(long)c * R + r] = __float2bfloat16(v - __bfloat162float(h));
        }
    }
}

// ---------------------------------------------------------------------------
// elementwise kernels
// ---------------------------------------------------------------------------
__device__ __forceinline__ float blockReduceSum(float v) {
    __shared__ float red[32];
    int lane = threadIdx.x & 31, w = threadIdx.x >> 5;
    #pragma unroll
    for (int o = 16; o; o >>= 1) v += __shfl_xor_sync(0xffffffffu, v, o);
    if (lane == 0) red[w] = v;
    __syncthreads();
    if (w == 0) {
        float x = (lane < (int)(blockDim.x >> 5)) ? red[lane] : 0.f;
        #pragma unroll
        for (int o = 16; o; o >>= 1) x += __shfl_xor_sync(0xffffffffu, x, o);
        if (lane == 0) red[0] = x;
    }
    __syncthreads();
    float r = red[0];
    __syncthreads();
    return r;
}
__device__ __forceinline__ float blockReduceMax(float v) {
    __shared__ float red[32];
    int lane = threadIdx.x & 31, w = threadIdx.x >> 5;
    #pragma unroll
    for (int o = 16; o; o >>= 1) v = fmaxf(v, __shfl_xor_sync(0xffffffffu, v, o));
    if (lane == 0) red[w] = v;
    __syncthreads();
    if (w == 0) {
        float x = (lane < (int)(blockDim.x >> 5)) ? red[lane] : -3.4e38f;
        #pragma unroll
        for (int o = 16; o; o >>= 1) x = fmaxf(x, __shfl_xor_sync(0xffffffffu, x, o));
        if (lane == 0) red[0] = x;
    }
    __syncthreads();
    float r = red[0];
    __syncthreads();
    return r;
}

__global__ void rmsnorm_kernel(const float* __restrict__ x,
                               const float* __restrict__ w,
                               float* __restrict__ out, int N) {
    long row = blockIdx.x;
    const float* xr = x + row * N;
    float* orow = out + row * N;
    float ss = 0.f;
    for (int i = threadIdx.x; i < N; i += blockDim.x) { float v = xr[i]; ss += v * v; }
    ss = blockReduceSum(ss);
    float inv = rsqrtf(ss / (float)N + EPS_);
    for (int i = threadIdx.x; i < N; i += blockDim.x) orow[i] = xr[i] * inv * w[i];
}

__global__ void kprep_kernel(const float* __restrict__ kv,
                             const float* __restrict__ w,
                             const float* __restrict__ cosT,
                             const float* __restrict__ sinT,
                             float* __restrict__ kf) {
    long s = blockIdx.x;
    const float* row = kv + s * CF_;
    float* krow = kf + s * CF_;
    float ss = 0.f;
    for (int i = threadIdx.x; i < KVL_; i += blockDim.x) { float v = row[i]; ss += v * v; }
    ss = blockReduceSum(ss);
    float inv = rsqrtf(ss / (float)KVL_ + EPS_);
    for (int i = threadIdx.x; i < KVL_; i += blockDim.x) krow[i] = row[i] * inv * w[i];
    int i = threadIdx.x;
    if (i < DR_) {
        float x = row[KVL_ + i];
        float rot = (i < DR_ / 2) ? -row[KVL_ + i + DR_ / 2] : row[KVL_ + i - DR_ / 2];
        krow[KVL_ + i] = x * cosT[s * DR_ + i] + rot * sinT[s * DR_ + i];
    }
}

__global__ void qrope_kernel(const float* __restrict__ q,
                             const float* __restrict__ cosT,
                             const float* __restrict__ sinT,
                             float* __restrict__ qf) {
    long s = blockIdx.x;
    int h = blockIdx.y;
    int i = threadIdx.x;
    const float* qp = q + s * (long)(H_ * DF_) + h * DF_ + DN_;
    float x = qp[i];
    float rot = (i < DR_ / 2) ? -qp[i + DR_ / 2] : qp[i - DR_ / 2];
    qf[((long)h * S_ + s) * CF_ + KVL_ + i] =
        x * cosT[s * DR_ + i] + rot * sinT[s * DR_ + i];
}

__global__ void softmax_causal_kernel(float* __restrict__ scores) {
    long s = blockIdx.x;
    int h = blockIdx.y;
    float* row = scores + ((long)h * S_ + s) * S_;
    int L = (int)s + 1;
    float m = -3.4e38f;
    for (int i = threadIdx.x; i < L; i += blockDim.x) m = fmaxf(m, row[i]);
    m = blockReduceMax(m);
    float sum = 0.f;
    for (int i = threadIdx.x; i < L; i += blockDim.x) {
        float e = __expf(row[i] - m);
        row[i] = e;
        sum += e;
    }
    sum = blockReduceSum(sum);
    float inv = 1.f / sum;
    for (int i = threadIdx.x; i < L; i += blockDim.x) row[i] *= inv;
    for (int i = L + threadIdx.x; i < S_; i += blockDim.x) row[i] = 0.f;
}

__global__ void swiglu_kernel(const float* __restrict__ gu, float* __restrict__ act) {
    long idx = (long)blockIdx.x * blockDim.x + threadIdx.x;
    if (idx >= (long)S_ * I_) return;
    long s = idx / I_, i = idx % I_;
    float g = gu[s * (2L * I_) + i];
    float u = gu[s * (2L * I_) + I_ + i];
    float si = g / (1.f + __expf(-g));
    act[idx] = si * u;
}

// ---------------------------------------------------------------------------
// host orchestration
// ---------------------------------------------------------------------------
static void launch_tc(const __nv_bfloat16* Ah, const __nv_bfloat16* Al, int lda, long sA,
                      const __nv_bfloat16* Bh, const __nv_bfloat16* Bl, int ldb, long sB,
                      float* C, int ldc, long sC,
                      int M, int N, int K, float alpha,
                      const float* add, int ldad, long sAd,
                      int batch, int causal) {
    dim3 grid((N + 127) / 128, (M + 127) / 128, batch);
    gemm_tc<<<grid, 256, GEMM_SMEM>>>(Ah, Al, lda, sA, Bh, Bl, ldb, sB,
                                      C, ldc, sC, M, N, K, alpha, add, ldad, sAd, causal);
}

extern "C" void kernel_launch(void* const* d_in, const int* in_sizes, int n_in,
                              void* d_out, int out_size) {
    const float* hidden    = (const float*)d_in[0];
    const float* cosT      = (const float*)d_in[1];
    const float* sinT      = (const float*)d_in[2];
    const float* ln1_w     = (const float*)d_in[3];
    const float* q_a_w     = (const float*)d_in[4];
    const float* q_a_ln_w  = (const float*)d_in[5];
    const float* q_b_w     = (const float*)d_in[6];
    const float* kv_a_w    = (const float*)d_in[7];
    const float* kv_a_ln_w = (const float*)d_in[8];
    const float* kc_w      = (const float*)d_in[9];
    const float* vc_w      = (const float*)d_in[10];
    const float* o_w       = (const float*)d_in[11];
    const float* ln2_w     = (const float*)d_in[12];
    const float* gate_up_w = (const float*)d_in[13];
    const float* down_w    = (const float*)d_in[14];
    float* out             = (float*)d_out;

    cudaFuncSetAttribute(gemm_tc, cudaFuncAttributeMaxDynamicSharedMemorySize, GEMM_SMEM);

    float* sc = nullptr;
    cudaGetSymbolAddress((void**)&sc, g_scratch);
    __nv_bfloat16* bf = nullptr;
    cudaGetSymbolAddress((void**)&bf, g_bf);

    float* h_     = sc + OFF_H;
    float* qa     = sc + OFF_QA;
    float* q      = sc + OFF_Q;
    float* kv     = sc + OFF_KV;
    float* kf     = sc + OFF_KF;
    float* qf     = sc + OFF_QF;
    float* scores = sc + OFF_SCORES;
    float* olat   = sc + OFF_OLAT;
    float* o      = sc + OFF_O;
    float* hid2   = sc + OFF_HID2;
    float* x2     = sc + OFF_X2;
    float* gu     = sc + OFF_GU;
    float* act    = sc + OFF_ACT;

    auto SPLIT = [&](const float* src, long off, long E) {
        long n4 = E / 4;
        split_rm<<<(unsigned)((n4 + 255) / 256), 256>>>(src, bf + off, bf + off + E, n4);
    };
    auto TSPLIT = [&](const float* src, long off, long E, int R, int C, int batch,
                      long sIn, long sOut) {
        dim3 grid((C + 31) / 32, (R + 31) / 32, batch);
        tsplit_kernel<<<grid, dim3(32, 8)>>>(src, bf + off, bf + off + E, R, C, sIn, sOut);
    };

    // --- weight transpose-splits (B-side operands become [n][k]) ---
    TSPLIT(q_a_w,     B_WQA,  E_WQA,  D_,  QL_,       1, 0, 0);
    TSPLIT(q_b_w,     B_WQB,  E_WQB,  QL_, H_ * DF_,  1, 0, 0);
    TSPLIT(kv_a_w,    B_WKVA, E_WKVA, D_,  CF_,       1, 0, 0);
    TSPLIT(kc_w,      B_WKC,  E_WKC,  DN_, KVL_, H_, (long)DN_ * KVL_, (long)DN_ * KVL_);
    TSPLIT(vc_w,      B_WVC,  E_WVC,  KVL_, DV_, H_, (long)KVL_ * DV_, (long)KVL_ * DV_);
    TSPLIT(o_w,       B_WO,   E_WO,   H_ * DV_, D_,  1, 0, 0);
    TSPLIT(gate_up_w, B_WGU,  E_WGU,  D_,  2 * I_,    1, 0, 0);
    TSPLIT(down_w,    B_WDN,  E_WDN,  I_,  D_,        1, 0, 0);

    // 1. h = rmsnorm(hidden, ln1_w); split
    rmsnorm_kernel<<<S_, 256>>>(hidden, ln1_w, h_, D_);
    SPLIT(h_, B_HS, E_HS);

    // 2. qa = h @ q_a_w
    launch_tc(bf + B_HS, bf + B_HS + E_HS, D_, 0,
              bf + B_WQA, bf + B_WQA + E_WQA, D_, 0,
              qa, QL_, 0, S_, QL_, D_, 1.f, nullptr, 0, 0, 1, 0);

    // 3. rmsnorm in place, split
    rmsnorm_kernel<<<S_, 256>>>(qa, q_a_ln_w, qa, QL_);
    SPLIT(qa, B_QAS, E_QAS);

    // 4. q = qa @ q_b_w
    launch_tc(bf + B_QAS, bf + B_QAS + E_QAS, QL_, 0,
              bf + B_WQB, bf + B_WQB + E_WQB, QL_, 0,
              q, H_ * DF_, 0, S_, H_ * DF_, QL_, 1.f, nullptr, 0, 0, 1, 0);

    // 5. kv = h @ kv_a_w
    launch_tc(bf + B_HS, bf + B_HS + E_HS, D_, 0,
              bf + B_WKVA, bf + B_WKVA + E_WKVA, D_, 0,
              kv, CF_, 0, S_, CF_, D_, 1.f, nullptr, 0, 0, 1, 0);

    // 6. kf prep; splits (row-major for scores-B, transposed for olat-B)
    kprep_kernel<<<S_, 256>>>(kv, kv_a_ln_w, cosT, sinT, kf);
    SPLIT(kf, B_KFS, E_KFS);
    TSPLIT(kf, B_KFT, E_KFT, S_, CF_, 1, 0, 0);

    // 7. split q; q_lat[h] = q_nope[h] @ kc_w[h]
    SPLIT(q, B_QS, E_QS);
    launch_tc(bf + B_QS, bf + B_QS + E_QS, H_ * DF_, (long)DF_,
              bf + B_WKC, bf + B_WKC + E_WKC, DN_, (long)KVL_ * DN_,
              qf, CF_, (long)S_ * CF_,
              S_, KVL_, DN_, 1.f, nullptr, 0, 0, H_, 0);

    // 8. q_pe rope into qf cols 512:576; split qf
    qrope_kernel<<<dim3(S_, H_), DR_>>>(q, cosT, sinT, qf);
    SPLIT(qf, B_QFS, E_QFS);

    // 9. scores[h] = SCALE * qf[h] @ kf^T (causal block skip)
    launch_tc(bf + B_QFS, bf + B_QFS + E_QFS, CF_, (long)S_ * CF_,
              bf + B_KFS, bf + B_KFS + E_KFS, CF_, 0,
              scores, S_, (long)S_ * S_,
              S_, S_, CF_, SCALE_, nullptr, 0, 0, H_, 1);

    // 10. softmax (zero-fills masked region)
    softmax_causal_kernel<<<dim3(S_, H_), 256>>>(scores);

    // 11. split attn; olat[h] = attn[h] @ k_lat  (K limited causally)
    SPLIT(scores, B_ATT, E_ATT);
    launch_tc(bf + B_ATT, bf + B_ATT + E_ATT, S_, (long)S_ * S_,
              bf + B_KFT, bf + B_KFT + E_KFT, S_, 0,
              olat, KVL_, (long)S_ * KVL_,
              S_, KVL_, S_, 1.f, nullptr, 0, 0, H_, 2);

    // 12. split olat; o[:, h*128:(h+1)*128] = olat[h] @ vc_w[h]
    SPLIT(olat, B_OLS, E_OLS);
    launch_tc(bf + B_OLS, bf + B_OLS + E_OLS, KVL_, (long)S_ * KVL_,
              bf + B_WVC, bf + B_WVC + E_WVC, KVL_, (long)KVL_ * DV_,
              o, H_ * DV_, (long)DV_,
              S_, DV_, KVL_, 1.f, nullptr, 0, 0, H_, 0);

    // 13. split o; hid2 = o @ o_w + hidden
    SPLIT(o, B_OS, E_OS);
    launch_tc(bf + B_OS, bf + B_OS + E_OS, H_ * DV_, 0,
              bf + B_WO, bf + B_WO + E_WO, H_ * DV_, 0,
              hid2, D_, 0, S_, D_, H_ * DV_, 1.f, hidden, D_, 0, 1, 0);

    // 14. x2 = rmsnorm(hid2); split
    rmsnorm_kernel<<<S_, 256>>>(hid2, ln2_w, x2, D_);
    SPLIT(x2, B_X2S, E_X2S);

    // 15. gu = x2 @ gate_up_w
    launch_tc(bf + B_X2S, bf + B_X2S + E_X2S, D_, 0,
              bf + B_WGU, bf + B_WGU + E_WGU, D_, 0,
              gu, 2 * I_, 0, S_, 2 * I_, D_, 1.f, nullptr, 0, 0, 1, 0);

    // 16. swiglu; split
    {
        long total = (long)S_ * I_;
        swiglu_kernel<<<(unsigned)((total + 255) / 256), 256>>>(gu, act);
    }
    SPLIT(act, B_ACTS, E_ACTS);

    // 17. out = act @ down_w + hid2
    launch_tc(bf + B_ACTS, bf + B_ACTS + E_ACTS, I_, 0,
              bf + B_WDN, bf + B_WDN + E_WDN, I_, 0,
              out, D_, 0, S_, D_, I_, 1.f, hid2, D_, 0, 1, 0);
}

// round 5
// speedup vs baseline: 3.4073x; 1.0808x over previous
#include <cuda_runtime.h>
#include <cuda_bf16.h>
#include <cstdint>
#include <math.h>

// ---------------------------------------------------------------------------
// DeepSeek V2 decoder layer via mma.sync HMMA (bf16 hi/lo split, fp32 acc).
// All splits fused into producers; B operands consumed in natural layout.
// ---------------------------------------------------------------------------

#define S_  2048
#define D_  2048
#define H_  16
#define QL_ 1536
#define KVL_ 512
#define DN_ 128
#define DR_ 64
#define DV_ 128
#define I_  8192
#define EPS_ 1e-6f
#define SCALE_ 0.07216878364870323f   // 192^-0.5
#define CF_ 576
#define DF_ 192

// ------------------------- fp32 scratch -------------------------------------
#define OFF_QA       0L
#define OFF_KV       (OFF_QA     + (long)S_*QL_)
#define OFF_SCORES   (OFF_KV     + (long)S_*CF_)
#define OFF_HID2     (OFF_SCORES + (long)H_*S_*S_)
#define OFF_GU       (OFF_HID2   + (long)S_*D_)
#define SCRATCH_TOTAL (OFF_GU    + (long)S_*2*I_)

__device__ __align__(256) float g_scratch[SCRATCH_TOTAL];

// ------------------- bf16 scratch (hi at OFF, lo at OFF+E) ------------------
#define E_HS    ((long)S_*D_)
#define E_QAS   ((long)S_*QL_)
#define E_QS    ((long)S_*H_*DF_)
#define E_QFS   ((long)H_*S_*CF_)
#define E_KFS   ((long)S_*CF_)
#define E_ATT   ((long)H_*S_*S_)
#define E_OLS   ((long)H_*S_*KVL_)
#define E_OS    ((long)S_*D_)
#define E_X2S   ((long)S_*D_)
#define E_ACTS  ((long)S_*I_)
#define E_WQA   ((long)D_*QL_)
#define E_WQB   ((long)QL_*H_*DF_)
#define E_WKVA  ((long)D_*CF_)
#define E_WKC   ((long)H_*DN_*KVL_)
#define E_WVC   ((long)H_*KVL_*DV_)
#define E_WO    ((long)D_*D_)
#define E_WGU   ((long)D_*2*I_)
#define E_WDN   ((long)I_*D_)

#define B_HS    0L
#define B_QAS   (B_HS   + 2*E_HS)
#define B_QS    (B_QAS  + 2*E_QAS)
#define B_QFS   (B_QS   + 2*E_QS)
#define B_KFS   (B_QFS  + 2*E_QFS)
#define B_ATT   (B_KFS  + 2*E_KFS)
#define B_OLS   (B_ATT  + 2*E_ATT)
#define B_OS    (B_OLS  + 2*E_OLS)
#define B_X2S   (B_OS   + 2*E_OS)
#define B_ACTS  (B_X2S  + 2*E_X2S)
#define B_WQA   (B_ACTS + 2*E_ACTS)
#define B_WQB   (B_WQA  + 2*E_WQA)
#define B_WKVA  (B_WQB  + 2*E_WQB)
#define B_WKC   (B_WKVA + 2*E_WKVA)
#define B_WVC   (B_WKC  + 2*E_WKC)
#define B_WO    (B_WVC  + 2*E_WVC)
#define B_WGU   (B_WO   + 2*E_WO)
#define B_WDN   (B_WGU  + 2*E_WGU)
#define BF_TOTAL (B_WDN + 2*E_WDN)

__device__ __align__(256) __nv_bfloat16 g_bf[BF_TOTAL];

// ---------------------------------------------------------------------------
// low-level helpers (base-target instructions only, sm_80+)
// ---------------------------------------------------------------------------
__device__ __forceinline__ uint32_t smem_u32(const void* p) {
    uint32_t a;
    asm("{ .reg .u64 t; cvta.to.shared.u64 t, %1; cvt.u32.u64 %0, t; }"
        : "=r"(a) : "l"(p));
    return a;
}
__device__ __forceinline__ void ldmat_x4(uint32_t* r, uint32_t addr) {
    asm volatile("ldmatrix.sync.aligned.m8n8.x4.shared.b16 {%0,%1,%2,%3}, [%4];"
                 : "=r"(r[0]), "=r"(r[1]), "=r"(r[2]), "=r"(r[3]) : "r"(addr));
}
__device__ __forceinline__ void ldmat_x4_t(uint32_t* r, uint32_t addr) {
    asm volatile("ldmatrix.sync.aligned.m8n8.x4.trans.shared.b16 {%0,%1,%2,%3}, [%4];"
                 : "=r"(r[0]), "=r"(r[1]), "=r"(r[2]), "=r"(r[3]) : "r"(addr));
}
__device__ __forceinline__ void mma16816(float* c, const uint32_t* a, const uint32_t* b) {
    asm volatile(
        "mma.sync.aligned.m16n8k16.row.col.f32.bf16.bf16.f32 "
        "{%0,%1,%2,%3}, {%4,%5,%6,%7}, {%8,%9}, {%0,%1,%2,%3};"
        : "+f"(c[0]), "+f"(c[1]), "+f"(c[2]), "+f"(c[3])
        : "r"(a[0]), "r"(a[1]), "r"(a[2]), "r"(a[3]), "r"(b[0]), "r"(b[1]));
}
__device__ __forceinline__ void cp_async16(uint32_t saddr, const void* gptr) {
    asm volatile("cp.async.cg.shared.global [%0], [%1], 16;"
                 :: "r"(saddr), "l"(__cvta_generic_to_global(gptr)));
}
#define CP_COMMIT() asm volatile("cp.async.commit_group;" ::: "memory")
#define CP_WAIT(n)  asm volatile("cp.async.wait_group %0;" :: "n"(n) : "memory")

__device__ __forceinline__ void zfill16(uint32_t saddr) {
    asm volatile("st.shared.v4.b32 [%0], {%1,%1,%1,%1};" :: "r"(saddr), "r"(0) : "memory");
}

// ---------------------------------------------------------------------------
// GEMM: out = alpha * sum_k A[m,k]*B(k,n) (+ add)
// A bf16 hi/lo row-major [M][lda].
// BTRANS=0: B bf16 hi/lo [N][ldb] (K contiguous).  BTRANS=1: B [K][ldb] (N contig).
// Output: Cf fp32 and/or (Chi,Clo) bf16 hi/lo split.
// causal: 0 none, 1 skip n0 > m0+127, 2 K limited to m0+128.
// 128x128x32 tile, 256 thr, 8 warps of 64x32. M must be a multiple of 128.
// ---------------------------------------------------------------------------
#define ROWA   80                          // 32 bf16 = 64B + 16B pad
#define TILE_A (128 * ROWA)                // 10240
#define ROWBT  272                         // 128 bf16 = 256B + 16B pad
#define TILE_BT (32 * ROWBT)               // 8704
#define TILE_BN (128 * ROWA)               // 10240

template <int BTRANS>
__global__ void __launch_bounds__(256, 1)
gemm_tc(const __nv_bfloat16* __restrict__ Ahi, const __nv_bfloat16* __restrict__ Alo,
        int lda, long sA,
        const __nv_bfloat16* __restrict__ Bhi, const __nv_bfloat16* __restrict__ Blo,
        int ldb, long sB,
        float* __restrict__ Cf,
        __nv_bfloat16* __restrict__ Chi, __nv_bfloat16* __restrict__ Clo,
        int ldc, long sC,
        int M, int N, int K, float alpha,
        const float* __restrict__ add, int ldad, long sAd,
        int causal) {
    constexpr int BSZ = BTRANS ? TILE_BT : TILE_BN;
    constexpr int STAGE = 2 * TILE_A + 2 * BSZ;

    const int m0 = blockIdx.x * 128;       // M fast-varying for L2 reuse of B
    const int n0 = blockIdx.y * 128;
    if (causal == 1 && n0 > m0 + 127) return;

    const int bz = blockIdx.z;
    Ahi += (long)bz * sA;  Alo += (long)bz * sA;
    Bhi += (long)bz * sB;  Blo += (long)bz * sB;
    if (Cf)  Cf  += (long)bz * sC;
    if (Chi) { Chi += (long)bz * sC; Clo += (long)bz * sC; }
    if (add) add += (long)bz * sAd;

    const int kmax = (causal == 2) ? min(K, m0 + 128) : K;
    const int nk = kmax / 32;

    extern __shared__ __align__(128) char smem[];
    const uint32_t sbase = smem_u32(smem);
    const int tid = threadIdx.x, lane = tid & 31, wid = tid >> 5;
    const int wm = wid & 1, wn = wid >> 1;

    float acc[4][4][4];
    #pragma unroll
    for (int i = 0; i < 4; i++)
        #pragma unroll
        for (int j = 0; j < 4; j++)
            #pragma unroll
            for (int r = 0; r < 4; r++) acc[i][j][r] = 0.f;

    auto load_stage = [&](int t) {
        const int k0 = t * 32;
        const uint32_t sb = sbase + (t & 1) * STAGE;
        // A: 128 rows x 64B x 2 precisions = 1024 x 16B chunks
        #pragma unroll
        for (int i = 0; i < 4; i++) {
            int idx = tid + i * 256;
            int prec = idx >> 9, r = (idx >> 2) & 127, ch = idx & 3;
            uint32_t sa = sb + prec * TILE_A + r * ROWA + ch * 16;
            const __nv_bfloat16* g = prec ? Alo : Ahi;
            cp_async16(sa, g + (long)(m0 + r) * lda + k0 + ch * 8);
        }
        // B
        if (BTRANS) {
            // 32 k-rows x 256B x 2 precisions = 1024 x 16B chunks
            #pragma unroll
            for (int i = 0; i < 4; i++) {
                int idx = tid + i * 256;
                int prec = idx >> 9, rem = idx & 511;
                int r = rem >> 4, ch = rem & 15;
                uint32_t sa = sb + 2 * TILE_A + prec * BSZ + r * ROWBT + ch * 16;
                if (n0 + ch * 8 < N) {
                    const __nv_bfloat16* g = prec ? Blo : Bhi;
                    cp_async16(sa, g + (long)(k0 + r) * ldb + n0 + ch * 8);
                } else {
                    zfill16(sa);
                }
            }
        } else {
            // 128 n-rows x 64B x 2 precisions
            #pragma unroll
            for (int i = 0; i < 4; i++) {
                int idx = tid + i * 256;
                int prec = idx >> 9, rem = idx & 511;
                int r = rem >> 2, ch = rem & 3;
                uint32_t sa = sb + 2 * TILE_A + prec * BSZ + r * ROWA + ch * 16;
                if (n0 + r < N) {
                    const __nv_bfloat16* g = prec ? Blo : Bhi;
                    cp_async16(sa, g + (long)(n0 + r) * ldb + k0 + ch * 8);
                } else {
                    zfill16(sa);
                }
            }
        }
        CP_COMMIT();
    };

    load_stage(0);
    for (int t = 0; t < nk; t++) {
        if (t + 1 < nk) { load_stage(t + 1); CP_WAIT(1); }
        else            { CP_WAIT(0); }
        __syncthreads();

        const uint32_t sb = sbase + (t & 1) * STAGE;
        #pragma unroll
        for (int kk = 0; kk < 2; kk++) {
            uint32_t ah[4][4], al[4][4];
            uint32_t bh[4][2], bl[4][2];
            #pragma unroll
            for (int mi = 0; mi < 4; mi++) {
                int row = wm * 64 + mi * 16 + (lane & 15);
                uint32_t a = sb + row * ROWA + kk * 32 + ((lane >> 4) & 1) * 16;
                ldmat_x4(ah[mi], a);
                ldmat_x4(al[mi], a + TILE_A);
            }
            if (BTRANS) {
                #pragma unroll
                for (int nb = 0; nb < 2; nb++) {
                    int krow = kk * 16 + (lane & 15);
                    int col = wn * 32 + nb * 16 + ((lane >> 4) & 1) * 8;
                    uint32_t a = sb + 2 * TILE_A + krow * ROWBT + col * 2;
                    uint32_t rh[4], rl[4];
                    ldmat_x4_t(rh, a);
                    ldmat_x4_t(rl, a + BSZ);
                    bh[2 * nb][0] = rh[0]; bh[2 * nb][1] = rh[1];
                    bh[2 * nb + 1][0] = rh[2]; bh[2 * nb + 1][1] = rh[3];
                    bl[2 * nb][0] = rl[0]; bl[2 * nb][1] = rl[1];
                    bl[2 * nb + 1][0] = rl[2]; bl[2 * nb + 1][1] = rl[3];
                }
            } else {
                #pragma unroll
                for (int nb = 0; nb < 2; nb++) {
                    int row = wn * 32 + nb * 16 + ((lane >> 4) & 1) * 8 + (lane & 7);
                    uint32_t a = sb + 2 * TILE_A + row * ROWA + kk * 32 + ((lane >> 3) & 1) * 16;
                    uint32_t rh[4], rl[4];
                    ldmat_x4(rh, a);
                    ldmat_x4(rl, a + BSZ);
                    bh[2 * nb][0] = rh[0]; bh[2 * nb][1] = rh[1];
                    bh[2 * nb + 1][0] = rh[2]; bh[2 * nb + 1][1] = rh[3];
                    bl[2 * nb][0] = rl[0]; bl[2 * nb][1] = rl[1];
                    bl[2 * nb + 1][0] = rl[2]; bl[2 * nb + 1][1] = rl[3];
                }
            }
            #pragma unroll
            for (int mi = 0; mi < 4; mi++)
                #pragma unroll
                for (int ni = 0; ni < 4; ni++) {
                    mma16816(acc[mi][ni], ah[mi], bh[ni]);
                    mma16816(acc[mi][ni], ah[mi], bl[ni]);
                    mma16816(acc[mi][ni], al[mi], bh[ni]);
                }
        }
        __syncthreads();
    }

    // epilogue
    #pragma unroll
    for (int mi = 0; mi < 4; mi++) {
        #pragma unroll
        for (int ni = 0; ni < 4; ni++) {
            long row = m0 + wm * 64 + mi * 16 + (lane >> 2);
            int col = n0 + wn * 32 + ni * 8 + (lane & 3) * 2;
            if (col >= N) continue;
            float vx0 = alpha * acc[mi][ni][0];
            float vy0 = alpha * acc[mi][ni][1];
            float vx1 = alpha * acc[mi][ni][2];
            float vy1 = alpha * acc[mi][ni][3];
            if (add) {
                float2 r0 = *(const float2*)&add[row * ldad + col];
                float2 r1 = *(const float2*)&add[(row + 8) * ldad + col];
                vx0 += r0.x; vy0 += r0.y; vx1 += r1.x; vy1 += r1.y;
            }
            if (Cf) {
                *(float2*)&Cf[row * ldc + col] = make_float2(vx0, vy0);
                *(float2*)&Cf[(row + 8) * ldc + col] = make_float2(vx1, vy1);
            }
            if (Chi) {
                __nv_bfloat16 h0 = __float2bfloat16(vx0), h1 = __float2bfloat16(vy0);
                __nv_bfloat16 h2 = __float2bfloat16(vx1), h3 = __float2bfloat16(vy1);
                *(__nv_bfloat162*)&Chi[row * ldc + col] = __nv_bfloat162(h0, h1);
                *(__nv_bfloat162*)&Chi[(row + 8) * ldc + col] = __nv_bfloat162(h2, h3);
                *(__nv_bfloat162*)&Clo[row * ldc + col] =
                    __nv_bfloat162(__float2bfloat16(vx0 - __bfloat162float(h0)),
                                   __float2bfloat16(vy0 - __bfloat162float(h1)));
                *(__nv_bfloat162*)&Clo[(row + 8) * ldc + col] =
                    __nv_bfloat162(__float2bfloat16(vx1 - __bfloat162float(h2)),
                                   __float2bfloat16(vy1 - __bfloat162float(h3)));
            }
        }
    }
}

// ---------------------------------------------------------------------------
// split (coalesced, element order preserved): fp32 -> bf16 hi + lo
// ---------------------------------------------------------------------------
__global__ void split_rm(const float* __restrict__ x,
                         __nv_bfloat16* __restrict__ hi,
                         __nv_bfloat16* __restrict__ lo, long n4) {
    long i = (long)blockIdx.x * blockDim.x + threadIdx.x;
    if (i >= n4) return;
    float4 v = ((const float4*)x)[i];
    __nv_bfloat16 h0 = __float2bfloat16(v.x), h1 = __float2bfloat16(v.y);
    __nv_bfloat16 h2 = __float2bfloat16(v.z), h3 = __float2bfloat16(v.w);
    __nv_bfloat162* hp = (__nv_bfloat162*)hi;
    __nv_bfloat162* lp = (__nv_bfloat162*)lo;
    hp[i * 2 + 0] = __nv_bfloat162(h0, h1);
    hp[i * 2 + 1] = __nv_bfloat162(h2, h3);
    lp[i * 2 + 0] = __nv_bfloat162(__float2bfloat16(v.x - __bfloat162float(h0)),
                                   __float2bfloat16(v.y - __bfloat162float(h1)));
    lp[i * 2 + 1] = __nv_bfloat162(__float2bfloat16(v.z - __bfloat162float(h2)),
                                   __float2bfloat16(v.w - __bfloat162float(h3)));
}

// ---------------------------------------------------------------------------
// block reductions
// ---------------------------------------------------------------------------
__device__ __forceinline__ float blockReduceSum(float v) {
    __shared__ float red[32];
    int lane = threadIdx.x & 31, w = threadIdx.x >> 5;
    #pragma unroll
    for (int o = 16; o; o >>= 1) v += __shfl_xor_sync(0xffffffffu, v, o);
    if (lane == 0) red[w] = v;
    __syncthreads();
    if (w == 0) {
        float x = (lane < (int)(blockDim.x >> 5)) ? red[lane] : 0.f;
        #pragma unroll
        for (int o = 16; o; o >>= 1) x += __shfl_xor_sync(0xffffffffu, x, o);
        if (lane == 0) red[0] = x;
    }
    __syncthreads();
    float r = red[0];
    __syncthreads();
    return r;
}
__device__ __forceinline__ float blockReduceMax(float v) {
    __shared__ float red[32];
    int lane = threadIdx.x & 31, w = threadIdx.x >> 5;
    #pragma unroll
    for (int o = 16; o; o >>= 1) v = fmaxf(v, __shfl_xor_sync(0xffffffffu, v, o));
    if (lane == 0) red[w] = v;
    __syncthreads();
    if (w == 0) {
        float x = (lane < (int)(blockDim.x >> 5)) ? red[lane] : -3.4e38f;
        #pragma unroll
        for (int o = 16; o; o >>= 1) x = fmaxf(x, __shfl_xor_sync(0xffffffffu, x, o));
        if (lane == 0) red[0] = x;
    }
    __syncthreads();
    float r = red[0];
    __syncthreads();
    return r;
}

// ---------------------------------------------------------------------------
// rmsnorm with fused hi/lo split output
// ---------------------------------------------------------------------------
__global__ void rmsnorm_split_kernel(const float* __restrict__ x,
                                     const float* __restrict__ w,
                                     __nv_bfloat16* __restrict__ hi,
                                     __nv_bfloat16* __restrict__ lo, int N) {
    long row = blockIdx.x;
    const float* xr = x + row * N;
    float ss = 0.f;
    for (int i = threadIdx.x; i < N; i += blockDim.x) { float v = xr[i]; ss += v * v; }
    ss = blockReduceSum(ss);
    float inv = rsqrtf(ss / (float)N + EPS_);
    for (int i = threadIdx.x; i < N; i += blockDim.x) {
        float v = xr[i] * inv * w[i];
        __nv_bfloat16 h = __float2bfloat16(v);
        hi[row * N + i] = h;
        lo[row * N + i] = __float2bfloat16(v - __bfloat162float(h));
    }
}

// ---------------------------------------------------------------------------
// k preparation: rmsnorm(kv[:, :512]) + rope(kv[:, 512:576]) -> kf hi/lo
// ---------------------------------------------------------------------------
__global__ void kprep_kernel(const float* __restrict__ kv,
                             const float* __restrict__ w,
                             const float* __restrict__ cosT,
                             const float* __restrict__ sinT,
                             __nv_bfloat16* __restrict__ kfh,
                             __nv_bfloat16* __restrict__ kfl) {
    long s = blockIdx.x;
    const float* row = kv + s * CF_;
    float ss = 0.f;
    for (int i = threadIdx.x; i < KVL_; i += blockDim.x) { float v = row[i]; ss += v * v; }
    ss = blockReduceSum(ss);
    float inv = rsqrtf(ss / (float)KVL_ + EPS_);
    for (int i = threadIdx.x; i < KVL_; i += blockDim.x) {
        float v = row[i] * inv * w[i];
        __nv_bfloat16 h = __float2bfloat16(v);
        kfh[s * CF_ + i] = h;
        kfl[s * CF_ + i] = __float2bfloat16(v - __bfloat162float(h));
    }
    int i = threadIdx.x;
    if (i < DR_) {
        float x = row[KVL_ + i];
        float rot = (i < DR_ / 2) ? -row[KVL_ + i + DR_ / 2] : row[KVL_ + i - DR_ / 2];
        float v = x * cosT[s * DR_ + i] + rot * sinT[s * DR_ + i];
        __nv_bfloat16 h = __float2bfloat16(v);
        kfh[s * CF_ + KVL_ + i] = h;
        kfl[s * CF_ + KVL_ + i] = __float2bfloat16(v - __bfloat162float(h));
    }
}

// ---------------------------------------------------------------------------
// q_pe rope: read q hi/lo, write qf hi/lo cols 512..575. grid (S, H), 64 thr
// ---------------------------------------------------------------------------
__global__ void qrope_kernel(const __nv_bfloat16* __restrict__ qh,
                             const __nv_bfloat16* __restrict__ ql,
                             const float* __restrict__ cosT,
                             const float* __restrict__ sinT,
                             __nv_bfloat16* __restrict__ qfh,
                             __nv_bfloat16* __restrict__ qfl) {
    long s = blockIdx.x;
    int h = blockIdx.y;
    int i = threadIdx.x;
    long base = s * (long)(H_ * DF_) + h * DF_ + DN_;
    float x = __bfloat162float(qh[base + i]) + __bfloat162float(ql[base + i]);
    int j = (i < DR_ / 2) ? (i + DR_ / 2) : (i - DR_ / 2);
    float xr = __bfloat162float(qh[base + j]) + __bfloat162float(ql[base + j]);
    float rot = (i < DR_ / 2) ? -xr : xr;
    float v = x * cosT[s * DR_ + i] + rot * sinT[s * DR_ + i];
    long o = ((long)h * S_ + s) * CF_ + KVL_ + i;
    __nv_bfloat16 hh = __float2bfloat16(v);
    qfh[o] = hh;
    qfl[o] = __float2bfloat16(v - __bfloat162float(hh));
}

// ---------------------------------------------------------------------------
// causal softmax: scores fp32 -> attn hi/lo bf16 (single pass, reg-cached)
// ---------------------------------------------------------------------------
__global__ void softmax_causal_kernel(const float* __restrict__ scores,
                                      __nv_bfloat16* __restrict__ ah,
                                      __nv_bfloat16* __restrict__ al) {
    long s = blockIdx.x;
    int h = blockIdx.y;
    const float* row = scores + ((long)h * S_ + s) * S_;
    __nv_bfloat16* hrow = ah + ((long)h * S_ + s) * S_;
    __nv_bfloat16* lrow = al + ((long)h * S_ + s) * S_;
    int L = (int)s + 1;
    float v[8];
    int cnt = 0;
    float m = -3.4e38f;
    for (int i = threadIdx.x; i < L; i += 256) { v[cnt] = row[i]; m = fmaxf(m, v[cnt]); cnt++; }
    m = blockReduceMax(m);
    float sum = 0.f;
    for (int j = 0; j < cnt; j++) { v[j] = __expf(v[j] - m); sum += v[j]; }
    sum = blockReduceSum(sum);
    float inv = 1.f / sum;
    cnt = 0;
    for (int i = threadIdx.x; i < L; i += 256) {
        float p = v[cnt++] * inv;
        __nv_bfloat16 hh = __float2bfloat16(p);
        hrow[i] = hh;
        lrow[i] = __float2bfloat16(p - __bfloat162float(hh));
    }
    __nv_bfloat16 z = __float2bfloat16(0.f);
    for (int i = L + threadIdx.x; i < S_; i += 256) { hrow[i] = z; lrow[i] = z; }
}

// ---------------------------------------------------------------------------
// swiglu: gu fp32 -> act hi/lo
// ---------------------------------------------------------------------------
__global__ void swiglu_kernel(const float* __restrict__ gu,
                              __nv_bfloat16* __restrict__ ah,
                              __nv_bfloat16* __restrict__ al) {
    long idx = (long)blockIdx.x * blockDim.x + threadIdx.x;
    if (idx >= (long)S_ * I_) return;
    long s = idx / I_, i = idx % I_;
    float g = gu[s * (2L * I_) + i];
    float u = gu[s * (2L * I_) + I_ + i];
    float v = (g / (1.f + __expf(-g))) * u;
    __nv_bfloat16 h = __float2bfloat16(v);
    ah[idx] = h;
    al[idx] = __float2bfloat16(v - __bfloat162float(h));
}

// ---------------------------------------------------------------------------
// host orchestration
// ---------------------------------------------------------------------------
#define SMEM_T  (2 * (2 * TILE_A + 2 * TILE_BT))   // 75776
#define SMEM_NT (2 * (2 * TILE_A + 2 * TILE_BN))   // 81920

struct GArgs {
    const __nv_bfloat16 *Ah, *Al, *Bh, *Bl;
    int lda, ldb, ldc, M, N, K, batch, causal, ldad;
    long sA, sB, sC, sAd;
    float *Cf, alpha;
    __nv_bfloat16 *Chi, *Clo;
    const float* add;
};

static void launch_g(bool btrans, const GArgs& a) {
    dim3 grid(a.M / 128, (a.N + 127) / 128, a.batch);
    if (btrans)
        gemm_tc<1><<<grid, 256, SMEM_T>>>(a.Ah, a.Al, a.lda, a.sA, a.Bh, a.Bl, a.ldb, a.sB,
                                          a.Cf, a.Chi, a.Clo, a.ldc, a.sC,
                                          a.M, a.N, a.K, a.alpha, a.add, a.ldad, a.sAd, a.causal);
    else
        gemm_tc<0><<<grid, 256, SMEM_NT>>>(a.Ah, a.Al, a.lda, a.sA, a.Bh, a.Bl, a.ldb, a.sB,
                                           a.Cf, a.Chi, a.Clo, a.ldc, a.sC,
                                           a.M, a.N, a.K, a.alpha, a.add, a.ldad, a.sAd, a.causal);
}

extern "C" void kernel_launch(void* const* d_in, const int* in_sizes, int n_in,
                              void* d_out, int out_size) {
    const float* hidden    = (const float*)d_in[0];
    const float* cosT      = (const float*)d_in[1];
    const float* sinT      = (const float*)d_in[2];
    const float* ln1_w     = (const float*)d_in[3];
    const float* q_a_w     = (const float*)d_in[4];
    const float* q_a_ln_w  = (const float*)d_in[5];
    const float* q_b_w     = (const float*)d_in[6];
    const float* kv_a_w    = (const float*)d_in[7];
    const float* kv_a_ln_w = (const float*)d_in[8];
    const float* kc_w      = (const float*)d_in[9];
    const float* vc_w      = (const float*)d_in[10];
    const float* o_w       = (const float*)d_in[11];
    const float* ln2_w     = (const float*)d_in[12];
    const float* gate_up_w = (const float*)d_in[13];
    const float* down_w    = (const float*)d_in[14];
    float* out             = (float*)d_out;

    cudaFuncSetAttribute(gemm_tc<1>, cudaFuncAttributeMaxDynamicSharedMemorySize, SMEM_T);
    cudaFuncSetAttribute(gemm_tc<0>, cudaFuncAttributeMaxDynamicSharedMemorySize, SMEM_NT);

    float* sc = nullptr;
    cudaGetSymbolAddress((void**)&sc, g_scratch);
    __nv_bfloat16* bf = nullptr;
    cudaGetSymbolAddress((void**)&bf, g_bf);

    float* qa     = sc + OFF_QA;
    float* kv     = sc + OFF_KV;
    float* scores = sc + OFF_SCORES;
    float* hid2   = sc + OFF_HID2;
    float* gu     = sc + OFF_GU;

    auto HI = [&](long off) { return bf + off; };
    auto LO = [&](long off, long E) { return bf + off + E; };

    auto SPLIT = [&](const float* src, long off, long E) {
        long n4 = E / 4;
        split_rm<<<(unsigned)((n4 + 255) / 256), 256>>>(src, HI(off), LO(off, E), n4);
    };

    // --- weight splits (coalesced, natural [k][n] layout kept) ---
    SPLIT(q_a_w,     B_WQA,  E_WQA);
    SPLIT(q_b_w,     B_WQB,  E_WQB);
    SPLIT(kv_a_w,    B_WKVA, E_WKVA);
    SPLIT(kc_w,      B_WKC,  E_WKC);
    SPLIT(vc_w,      B_WVC,  E_WVC);
    SPLIT(o_w,       B_WO,   E_WO);
    SPLIT(gate_up_w, B_WGU,  E_WGU);
    SPLIT(down_w,    B_WDN,  E_WDN);

    // 1. h = rmsnorm(hidden) -> hi/lo
    rmsnorm_split_kernel<<<S_, 256>>>(hidden, ln1_w, HI(B_HS), LO(B_HS, E_HS), D_);

    GArgs a{};

    // 2. qa = h @ q_a_w  (fp32 out for rmsnorm)
    a = {HI(B_HS), LO(B_HS, E_HS), HI(B_WQA), LO(B_WQA, E_WQA),
         D_, QL_, QL_, S_, QL_, D_, 1, 0, 0, 0, 0, 0, 0,
         qa, 1.f, nullptr, nullptr, nullptr};
    launch_g(true, a);

    // 3. qas = rmsnorm(qa) -> hi/lo
    rmsnorm_split_kernel<<<S_, 256>>>(qa, q_a_ln_w, HI(B_QAS), LO(B_QAS, E_QAS), QL_);

    // 4. q = qas @ q_b_w -> hi/lo
    a = {HI(B_QAS), LO(B_QAS, E_QAS), HI(B_WQB), LO(B_WQB, E_WQB),
         QL_, H_ * DF_, H_ * DF_, S_, H_ * DF_, QL_, 1, 0, 0, 0, 0, 0, 0,
         nullptr, 1.f, HI(B_QS), LO(B_QS, E_QS), nullptr};
    launch_g(true, a);

    // 5. kv = h @ kv_a_w  (fp32 out for kprep; N=576)
    a = {HI(B_HS), LO(B_HS, E_HS), HI(B_WKVA), LO(B_WKVA, E_WKVA),
         D_, CF_, CF_, S_, CF_, D_, 1, 0, 0, 0, 0, 0, 0,
         kv, 1.f, nullptr, nullptr, nullptr};
    launch_g(true, a);

    // 6. kf = [rmsnorm(kv_lat), rope(k_pe)] -> hi/lo
    kprep_kernel<<<S_, 256>>>(kv, kv_a_ln_w, cosT, sinT, HI(B_KFS), LO(B_KFS, E_KFS));

    // 7. qf[:, :512] = q_nope @ kc_w per head -> hi/lo into qf
    a = {HI(B_QS), LO(B_QS, E_QS), HI(B_WKC), LO(B_WKC, E_WKC),
         H_ * DF_, KVL_, CF_, S_, KVL_, DN_, H_, 0, 0,
         (long)DF_, (long)DN_ * KVL_, (long)S_ * CF_, 0,
         nullptr, 1.f, HI(B_QFS), LO(B_QFS, E_QFS), nullptr};
    launch_g(true, a);

    // 8. qf[:, 512:576] = rope(q_pe) -> hi/lo
    qrope_kernel<<<dim3(S_, H_), DR_>>>(HI(B_QS), LO(B_QS, E_QS), cosT, sinT,
                                        HI(B_QFS), LO(B_QFS, E_QFS));

    // 9. scores = SCALE * qf @ kf^T  (B = kf [n][k], non-trans; causal skip)
    a = {HI(B_QFS), LO(B_QFS, E_QFS), HI(B_KFS), LO(B_KFS, E_KFS),
         CF_, CF_, S_, S_, S_, CF_, H_, 1, 0,
         (long)S_ * CF_, 0, (long)S_ * S_, 0,
         scores, SCALE_, nullptr, nullptr, nullptr};
    launch_g(false, a);

    // 10. softmax -> attn hi/lo (zero-fills masked tail)
    softmax_causal_kernel<<<dim3(S_, H_), 256>>>(scores, HI(B_ATT), LO(B_ATT, E_ATT));

    // 11. olat = attn @ k_lat  (B = kf [k=t][n=c], trans; K causal-limited)
    a = {HI(B_ATT), LO(B_ATT, E_ATT), HI(B_KFS), LO(B_KFS, E_KFS),
         S_, CF_, KVL_, S_, KVL_, S_, H_, 2, 0,
         (long)S_ * S_, 0, (long)S_ * KVL_, 0,
         nullptr, 1.f, HI(B_OLS), LO(B_OLS, E_OLS), nullptr};
    launch_g(true, a);

    // 12. o[:, h*128:] = olat @ vc_w per head -> hi/lo
    a = {HI(B_OLS), LO(B_OLS, E_OLS), HI(B_WVC), LO(B_WVC, E_WVC),
         KVL_, DV_, H_ * DV_, S_, DV_, KVL_, H_, 0, 0,
         (long)S_ * KVL_, (long)KVL_ * DV_, (long)DV_, 0,
         nullptr, 1.f, HI(B_OS), LO(B_OS, E_OS), nullptr};
    launch_g(true, a);

    // 13. hid2 = o @ o_w + hidden  (fp32)
    a = {HI(B_OS), LO(B_OS, E_OS), HI(B_WO), LO(B_WO, E_WO),
         H_ * DV_, D_, D_, S_, D_, H_ * DV_, 1, 0, D_, 0, 0, 0, 0,
         hid2, 1.f, nullptr, nullptr, hidden};
    launch_g(true, a);

    // 14. x2 = rmsnorm(hid2) -> hi/lo
    rmsnorm_split_kernel<<<S_, 256>>>(hid2, ln2_w, HI(B_X2S), LO(B_X2S, E_X2S), D_);

    // 15. gu = x2 @ gate_up_w  (fp32)
    a = {HI(B_X2S), LO(B_X2S, E_X2S), HI(B_WGU), LO(B_WGU, E_WGU),
         D_, 2 * I_, 2 * I_, S_, 2 * I_, D_, 1, 0, 0, 0, 0, 0, 0,
         gu, 1.f, nullptr, nullptr, nullptr};
    launch_g(true, a);

    // 16. act = swiglu(gu) -> hi/lo
    {
        long total = (long)S_ * I_;
        swiglu_kernel<<<(unsigned)((total + 255) / 256), 256>>>(gu, HI(B_ACTS), LO(B_ACTS, E_ACTS));
    }

    // 17. out = act @ down_w + hid2  (fp32)
    a = {HI(B_ACTS), LO(B_ACTS, E_ACTS), HI(B_WDN), LO(B_WDN, E_WDN),
         I_, D_, D_, S_, D_, I_, 1, 0, D_, 0, 0, 0, 0,
         out, 1.f, nullptr, nullptr, hid2};
    launch_g(true, a);
}

// round 7
// speedup vs baseline: 4.1743x; 1.2251x over previous
#include <cuda_runtime.h>
#include <cuda_bf16.h>
#include <cstdint>
#include <math.h>

// ---------------------------------------------------------------------------
// DeepSeek V2 decoder layer via mma.sync HMMA (bf16 hi/lo split, fp32 acc).
// 4-warp GEMM CTAs (2/SM), fused qa+kv projection, trimmed softmax fill.
// ---------------------------------------------------------------------------

#define S_  2048
#define D_  2048
#define H_  16
#define QL_ 1536
#define KVL_ 512
#define DN_ 128
#define DR_ 64
#define DV_ 128
#define I_  8192
#define EPS_ 1e-6f
#define SCALE_ 0.07216878364870323f   // 192^-0.5
#define CF_ 576
#define DF_ 192
#define NQKV_ 2112                    // QL + CF

// ------------------------- fp32 scratch -------------------------------------
#define OFF_QKV      0L
#define OFF_SCORES   (OFF_QKV    + (long)S_*NQKV_)
#define OFF_HID2     (OFF_SCORES + (long)H_*S_*S_)
#define OFF_GU       (OFF_HID2   + (long)S_*D_)
#define SCRATCH_TOTAL (OFF_GU    + (long)S_*2*I_)

__device__ __align__(256) float g_scratch[SCRATCH_TOTAL];

// ------------------- bf16 scratch (hi at OFF, lo at OFF+E) ------------------
#define E_HS    ((long)S_*D_)
#define E_QAS   ((long)S_*QL_)
#define E_QS    ((long)S_*H_*DF_)
#define E_QFS   ((long)H_*S_*CF_)
#define E_KFS   ((long)S_*CF_)
#define E_ATT   ((long)H_*S_*S_)
#define E_OLS   ((long)H_*S_*KVL_)
#define E_OS    ((long)S_*D_)
#define E_X2S   ((long)S_*D_)
#define E_ACTS  ((long)S_*I_)
#define E_WQKV  ((long)D_*NQKV_)
#define E_WQB   ((long)QL_*H_*DF_)
#define E_WKC   ((long)H_*DN_*KVL_)
#define E_WVC   ((long)H_*KVL_*DV_)
#define E_WO    ((long)D_*D_)
#define E_WGU   ((long)D_*2*I_)
#define E_WDN   ((long)I_*D_)

#define B_HS    0L
#define B_QAS   (B_HS   + 2*E_HS)
#define B_QS    (B_QAS  + 2*E_QAS)
#define B_QFS   (B_QS   + 2*E_QS)
#define B_KFS   (B_QFS  + 2*E_QFS)
#define B_ATT   (B_KFS  + 2*E_KFS)
#define B_OLS   (B_ATT  + 2*E_ATT)
#define B_OS    (B_OLS  + 2*E_OLS)
#define B_X2S   (B_OS   + 2*E_OS)
#define B_ACTS  (B_X2S  + 2*E_X2S)
#define B_WQKV  (B_ACTS + 2*E_ACTS)
#define B_WQB   (B_WQKV + 2*E_WQKV)
#define B_WKC   (B_WQB  + 2*E_WQB)
#define B_WVC   (B_WKC  + 2*E_WKC)
#define B_WO    (B_WVC  + 2*E_WVC)
#define B_WGU   (B_WO   + 2*E_WO)
#define B_WDN   (B_WGU  + 2*E_WGU)
#define BF_TOTAL (B_WDN + 2*E_WDN)

__device__ __align__(256) __nv_bfloat16 g_bf[BF_TOTAL];

// ---------------------------------------------------------------------------
// low-level helpers (base-target instructions only, sm_80+)
// ---------------------------------------------------------------------------
__device__ __forceinline__ uint32_t smem_u32(const void* p) {
    uint32_t a;
    asm("{ .reg .u64 t; cvta.to.shared.u64 t, %1; cvt.u32.u64 %0, t; }"
        : "=r"(a) : "l"(p));
    return a;
}
__device__ __forceinline__ void ldmat_x4(uint32_t* r, uint32_t addr) {
    asm volatile("ldmatrix.sync.aligned.m8n8.x4.shared.b16 {%0,%1,%2,%3}, [%4];"
                 : "=r"(r[0]), "=r"(r[1]), "=r"(r[2]), "=r"(r[3]) : "r"(addr));
}
__device__ __forceinline__ void ldmat_x4_t(uint32_t* r, uint32_t addr) {
    asm volatile("ldmatrix.sync.aligned.m8n8.x4.trans.shared.b16 {%0,%1,%2,%3}, [%4];"
                 : "=r"(r[0]), "=r"(r[1]), "=r"(r[2]), "=r"(r[3]) : "r"(addr));
}
__device__ __forceinline__ void mma16816(float* c, const uint32_t* a, const uint32_t* b) {
    asm volatile(
        "mma.sync.aligned.m16n8k16.row.col.f32.bf16.bf16.f32 "
        "{%0,%1,%2,%3}, {%4,%5,%6,%7}, {%8,%9}, {%0,%1,%2,%3};"
        : "+f"(c[0]), "+f"(c[1]), "+f"(c[2]), "+f"(c[3])
        : "r"(a[0]), "r"(a[1]), "r"(a[2]), "r"(a[3]), "r"(b[0]), "r"(b[1]));
}
__device__ __forceinline__ void cp_async16(uint32_t saddr, const void* gptr) {
    asm volatile("cp.async.cg.shared.global [%0], [%1], 16;"
                 :: "r"(saddr), "l"(__cvta_generic_to_global(gptr)));
}
#define CP_COMMIT() asm volatile("cp.async.commit_group;" ::: "memory")
#define CP_WAIT(n)  asm volatile("cp.async.wait_group %0;" :: "n"(n) : "memory")

__device__ __forceinline__ void zfill16(uint32_t saddr) {
    asm volatile("st.shared.v4.b32 [%0], {%1,%1,%1,%1};" :: "r"(saddr), "r"(0) : "memory");
}

// ---------------------------------------------------------------------------
// GEMM: out = alpha * sum_k A[m,k]*B(k,n) (+ add)
// A bf16 hi/lo row-major [M][lda].
// BTRANS=0: B bf16 hi/lo [N][ldb] (K contig). BTRANS=1: B [K][ldb] (N contig).
// 128x128x32 CTA tile, 128 threads (4 warps of 64x64), 2 CTAs/SM.
// causal: 0 none, 1 skip n0 > m0+127, 2 K limited to m0+128.
// ---------------------------------------------------------------------------
#define ROWA   80                          // 32 bf16 = 64B + 16B pad
#define TILE_A (128 * ROWA)                // 10240
#define ROWBT  272                         // 128 bf16 = 256B + 16B pad
#define TILE_BT (32 * ROWBT)               // 8704
#define TILE_BN (128 * ROWA)               // 10240

template <int BTRANS>
__global__ void __launch_bounds__(128, 2)
gemm_tc(const __nv_bfloat16* __restrict__ Ahi, const __nv_bfloat16* __restrict__ Alo,
        int lda, long sA,
        const __nv_bfloat16* __restrict__ Bhi, const __nv_bfloat16* __restrict__ Blo,
        int ldb, long sB,
        float* __restrict__ Cf,
        __nv_bfloat16* __restrict__ Chi, __nv_bfloat16* __restrict__ Clo,
        int ldc, long sC,
        int M, int N, int K, float alpha,
        const float* __restrict__ add, int ldad, long sAd,
        int causal) {
    constexpr int BSZ = BTRANS ? TILE_BT : TILE_BN;
    constexpr int STAGE = 2 * TILE_A + 2 * BSZ;

    const int m0 = blockIdx.x * 128;       // M fast-varying: L2 reuse of B
    const int n0 = blockIdx.y * 128;
    if (causal == 1 && n0 > m0 + 127) return;

    const int bz = blockIdx.z;
    Ahi += (long)bz * sA;  Alo += (long)bz * sA;
    Bhi += (long)bz * sB;  Blo += (long)bz * sB;
    if (Cf)  Cf  += (long)bz * sC;
    if (Chi) { Chi += (long)bz * sC; Clo += (long)bz * sC; }
    if (add) add += (long)bz * sAd;

    const int kmax = (causal == 2) ? min(K, m0 + 128) : K;
    const int nk = kmax / 32;

    extern __shared__ __align__(128) char smem[];
    const uint32_t sbase = smem_u32(smem);
    const int tid = threadIdx.x, lane = tid & 31, wid = tid >> 5;
    const int wm = wid & 1, wn = wid >> 1;  // warp tile: rows wm*64, cols wn*64

    float acc[4][8][4];
    #pragma unroll
    for (int i = 0; i < 4; i++)
        #pragma unroll
        for (int j = 0; j < 8; j++)
            #pragma unroll
            for (int r = 0; r < 4; r++) acc[i][j][r] = 0.f;

    auto load_stage = [&](int t) {
        const int k0 = t * 32;
        const uint32_t sb = sbase + (t & 1) * STAGE;
        // A: 128 rows x 64B x 2 precisions = 1024 x 16B chunks / 128 threads
        #pragma unroll
        for (int i = 0; i < 8; i++) {
            int idx = tid + i * 128;
            int prec = idx >> 9, r = (idx >> 2) & 127, ch = idx & 3;
            uint32_t sa = sb + prec * TILE_A + r * ROWA + ch * 16;
            const __nv_bfloat16* g = prec ? Alo : Ahi;
            cp_async16(sa, g + (long)(m0 + r) * lda + k0 + ch * 8);
        }
        if (BTRANS) {
            #pragma unroll
            for (int i = 0; i < 8; i++) {
                int idx = tid + i * 128;
                int prec = idx >> 9, rem = idx & 511;
                int r = rem >> 4, ch = rem & 15;
                uint32_t sa = sb + 2 * TILE_A + prec * BSZ + r * ROWBT + ch * 16;
                if (n0 + ch * 8 < N) {
                    const __nv_bfloat16* g = prec ? Blo : Bhi;
                    cp_async16(sa, g + (long)(k0 + r) * ldb + n0 + ch * 8);
                } else {
                    zfill16(sa);
                }
            }
        } else {
            #pragma unroll
            for (int i = 0; i < 8; i++) {
                int idx = tid + i * 128;
                int prec = idx >> 9, rem = idx & 511;
                int r = rem >> 2, ch = rem & 3;
                uint32_t sa = sb + 2 * TILE_A + prec * BSZ + r * ROWA + ch * 16;
                if (n0 + r < N) {
                    const __nv_bfloat16* g = prec ? Blo : Bhi;
                    cp_async16(sa, g + (long)(n0 + r) * ldb + k0 + ch * 8);
                } else {
                    zfill16(sa);
                }
            }
        }
        CP_COMMIT();
    };

    load_stage(0);
    for (int t = 0; t < nk; t++) {
        if (t + 1 < nk) { load_stage(t + 1); CP_WAIT(1); }
        else            { CP_WAIT(0); }
        __syncthreads();

        const uint32_t sb = sbase + (t & 1) * STAGE;
        #pragma unroll
        for (int kk = 0; kk < 2; kk++) {
            uint32_t ah[4][4], al[4][4];
            uint32_t bh[8][2], bl[8][2];
            #pragma unroll
            for (int mi = 0; mi < 4; mi++) {
                int row = wm * 64 + mi * 16 + (lane & 15);
                uint32_t a = sb + row * ROWA + kk * 32 + ((lane >> 4) & 1) * 16;
                ldmat_x4(ah[mi], a);
                ldmat_x4(al[mi], a + TILE_A);
            }
            if (BTRANS) {
                #pragma unroll
                for (int nb = 0; nb < 4; nb++) {
                    int krow = kk * 16 + (lane & 15);
                    int col = wn * 64 + nb * 16 + ((lane >> 4) & 1) * 8;
                    uint32_t a = sb + 2 * TILE_A + krow * ROWBT + col * 2;
                    uint32_t rh[4], rl[4];
                    ldmat_x4_t(rh, a);
                    ldmat_x4_t(rl, a + BSZ);
                    bh[2 * nb][0] = rh[0]; bh[2 * nb][1] = rh[1];
                    bh[2 * nb + 1][0] = rh[2]; bh[2 * nb + 1][1] = rh[3];
                    bl[2 * nb][0] = rl[0]; bl[2 * nb][1] = rl[1];
                    bl[2 * nb + 1][0] = rl[2]; bl[2 * nb + 1][1] = rl[3];
                }
            } else {
                #pragma unroll
                for (int nb = 0; nb < 4; nb++) {
                    int row = wn * 64 + nb * 16 + ((lane >> 4) & 1) * 8 + (lane & 7);
                    uint32_t a = sb + 2 * TILE_A + row * ROWA + kk * 32 + ((lane >> 3) & 1) * 16;
                    uint32_t rh[4], rl[4];
                    ldmat_x4(rh, a);
                    ldmat_x4(rl, a + BSZ);
                    bh[2 * nb][0] = rh[0]; bh[2 * nb][1] = rh[1];
                    bh[2 * nb + 1][0] = rh[2]; bh[2 * nb + 1][1] = rh[3];
                    bl[2 * nb][0] = rl[0]; bl[2 * nb][1] = rl[1];
                    bl[2 * nb + 1][0] = rl[2]; bl[2 * nb + 1][1] = rl[3];
                }
            }
            #pragma unroll
            for (int mi = 0; mi < 4; mi++)
                #pragma unroll
                for (int ni = 0; ni < 8; ni++) {
                    mma16816(acc[mi][ni], ah[mi], bh[ni]);
                    mma16816(acc[mi][ni], ah[mi], bl[ni]);
                    mma16816(acc[mi][ni], al[mi], bh[ni]);
                }
        }
        __syncthreads();
    }

    // epilogue
    #pragma unroll
    for (int mi = 0; mi < 4; mi++) {
        #pragma unroll
        for (int ni = 0; ni < 8; ni++) {
            long row = m0 + wm * 64 + mi * 16 + (lane >> 2);
            int col = n0 + wn * 64 + ni * 8 + (lane & 3) * 2;
            if (col >= N) continue;
            float vx0 = alpha * acc[mi][ni][0];
            float vy0 = alpha * acc[mi][ni][1];
            float vx1 = alpha * acc[mi][ni][2];
            float vy1 = alpha * acc[mi][ni][3];
            if (add) {
                float2 r0 = *(const float2*)&add[row * ldad + col];
                float2 r1 = *(const float2*)&add[(row + 8) * ldad + col];
                vx0 += r0.x; vy0 += r0.y; vx1 += r1.x; vy1 += r1.y;
            }
            if (Cf) {
                *(float2*)&Cf[row * ldc + col] = make_float2(vx0, vy0);
                *(float2*)&Cf[(row + 8) * ldc + col] = make_float2(vx1, vy1);
            }
            if (Chi) {
                __nv_bfloat16 h0 = __float2bfloat16(vx0), h1 = __float2bfloat16(vy0);
                __nv_bfloat16 h2 = __float2bfloat16(vx1), h3 = __float2bfloat16(vy1);
                *(__nv_bfloat162*)&Chi[row * ldc + col] = __nv_bfloat162(h0, h1);
                *(__nv_bfloat162*)&Chi[(row + 8) * ldc + col] = __nv_bfloat162(h2, h3);
                *(__nv_bfloat162*)&Clo[row * ldc + col] =
                    __nv_bfloat162(__float2bfloat16(vx0 - __bfloat162float(h0)),
                                   __float2bfloat16(vy0 - __bfloat162float(h1)));
                *(__nv_bfloat162*)&Clo[(row + 8) * ldc + col] =
                    __nv_bfloat162(__float2bfloat16(vx1 - __bfloat162float(h2)),
                                   __float2bfloat16(vy1 - __bfloat162float(h3)));
            }
        }
    }
}

// ---------------------------------------------------------------------------
// splits: fp32 -> bf16 hi + lo (contiguous, and strided-destination)
// ---------------------------------------------------------------------------
__global__ void split_rm(const float* __restrict__ x,
                         __nv_bfloat16* __restrict__ hi,
                         __nv_bfloat16* __restrict__ lo, long n4) {
    long i = (long)blockIdx.x * blockDim.x + threadIdx.x;
    if (i >= n4) return;
    float4 v = ((const float4*)x)[i];
    __nv_bfloat16 h0 = __float2bfloat16(v.x), h1 = __float2bfloat16(v.y);
    __nv_bfloat16 h2 = __float2bfloat16(v.z), h3 = __float2bfloat16(v.w);
    __nv_bfloat162* hp = (__nv_bfloat162*)hi;
    __nv_bfloat162* lp = (__nv_bfloat162*)lo;
    hp[i * 2 + 0] = __nv_bfloat162(h0, h1);
    hp[i * 2 + 1] = __nv_bfloat162(h2, h3);
    lp[i * 2 + 0] = __nv_bfloat162(__float2bfloat16(v.x - __bfloat162float(h0)),
                                   __float2bfloat16(v.y - __bfloat162float(h1)));
    lp[i * 2 + 1] = __nv_bfloat162(__float2bfloat16(v.z - __bfloat162float(h2)),
                                   __float2bfloat16(v.w - __bfloat162float(h3)));
}

// split src [R][C] (contiguous) into dst hi/lo [R][ldd] at column offset col0
__global__ void split_stride(const float* __restrict__ x,
                             __nv_bfloat16* __restrict__ hi,
                             __nv_bfloat16* __restrict__ lo,
                             int C, int ldd, int col0, long n4) {
    long i = (long)blockIdx.x * blockDim.x + threadIdx.x;
    if (i >= n4) return;
    float4 v = ((const float4*)x)[i];
    long e = i * 4;
    long r = e / C, c = e % C;
    long o = r * ldd + col0 + c;
    __nv_bfloat16 h0 = __float2bfloat16(v.x), h1 = __float2bfloat16(v.y);
    __nv_bfloat16 h2 = __float2bfloat16(v.z), h3 = __float2bfloat16(v.w);
    *(__nv_bfloat162*)&hi[o]     = __nv_bfloat162(h0, h1);
    *(__nv_bfloat162*)&hi[o + 2] = __nv_bfloat162(h2, h3);
    *(__nv_bfloat162*)&lo[o]     = __nv_bfloat162(__float2bfloat16(v.x - __bfloat162float(h0)),
                                                  __float2bfloat16(v.y - __bfloat162float(h1)));
    *(__nv_bfloat162*)&lo[o + 2] = __nv_bfloat162(__float2bfloat16(v.z - __bfloat162float(h2)),
                                                  __float2bfloat16(v.w - __bfloat162float(h3)));
}

// ---------------------------------------------------------------------------
// block reductions
// ---------------------------------------------------------------------------
__device__ __forceinline__ float blockReduceSum(float v) {
    __shared__ float red[32];
    int lane = threadIdx.x & 31, w = threadIdx.x >> 5;
    #pragma unroll
    for (int o = 16; o; o >>= 1) v += __shfl_xor_sync(0xffffffffu, v, o);
    if (lane == 0) red[w] = v;
    __syncthreads();
    if (w == 0) {
        float x = (lane < (int)(blockDim.x >> 5)) ? red[lane] : 0.f;
        #pragma unroll
        for (int o = 16; o; o >>= 1) x += __shfl_xor_sync(0xffffffffu, x, o);
        if (lane == 0) red[0] = x;
    }
    __syncthreads();
    float r = red[0];
    __syncthreads();
    return r;
}
__device__ __forceinline__ float blockReduceMax(float v) {
    __shared__ float red[32];
    int lane = threadIdx.x & 31, w = threadIdx.x >> 5;
    #pragma unroll
    for (int o = 16; o; o >>= 1) v = fmaxf(v, __shfl_xor_sync(0xffffffffu, v, o));
    if (lane == 0) red[w] = v;
    __syncthreads();
    if (w == 0) {
        float x = (lane < (int)(blockDim.x >> 5)) ? red[lane] : -3.4e38f;
        #pragma unroll
        for (int o = 16; o; o >>= 1) x = fmaxf(x, __shfl_xor_sync(0xffffffffu, x, o));
        if (lane == 0) red[0] = x;
    }
    __syncthreads();
    float r = red[0];
    __syncthreads();
    return r;
}

// ---------------------------------------------------------------------------
// rmsnorm with strided input and fused hi/lo split output
// ---------------------------------------------------------------------------
__global__ void rmsnorm_split_kernel(const float* __restrict__ x, int ldx,
                                     const float* __restrict__ w,
                                     __nv_bfloat16* __restrict__ hi,
                                     __nv_bfloat16* __restrict__ lo, int N) {
    long row = blockIdx.x;
    const float* xr = x + row * ldx;
    float ss = 0.f;
    for (int i = threadIdx.x; i < N; i += blockDim.x) { float v = xr[i]; ss += v * v; }
    ss = blockReduceSum(ss);
    float inv = rsqrtf(ss / (float)N + EPS_);
    for (int i = threadIdx.x; i < N; i += blockDim.x) {
        float v = xr[i] * inv * w[i];
        __nv_bfloat16 h = __float2bfloat16(v);
        hi[row * N + i] = h;
        lo[row * N + i] = __float2bfloat16(v - __bfloat162float(h));
    }
}

// ---------------------------------------------------------------------------
// k preparation: rmsnorm(kv[:, :512]) + rope(kv[:, 512:576]) -> kf hi/lo
// kv rows live at stride NQKV_, column offset QL_
// ---------------------------------------------------------------------------
__global__ void kprep_kernel(const float* __restrict__ qkv,
                             const float* __restrict__ w,
                             const float* __restrict__ cosT,
                             const float* __restrict__ sinT,
                             __nv_bfloat16* __restrict__ kfh,
                             __nv_bfloat16* __restrict__ kfl) {
    long s = blockIdx.x;
    const float* row = qkv + s * NQKV_ + QL_;
    float ss = 0.f;
    for (int i = threadIdx.x; i < KVL_; i += blockDim.x) { float v = row[i]; ss += v * v; }
    ss = blockReduceSum(ss);
    float inv = rsqrtf(ss / (float)KVL_ + EPS_);
    for (int i = threadIdx.x; i < KVL_; i += blockDim.x) {
        float v = row[i] * inv * w[i];
        __nv_bfloat16 h = __float2bfloat16(v);
        kfh[s * CF_ + i] = h;
        kfl[s * CF_ + i] = __float2bfloat16(v - __bfloat162float(h));
    }
    int i = threadIdx.x;
    if (i < DR_) {
        float x = row[KVL_ + i];
        float rot = (i < DR_ / 2) ? -row[KVL_ + i + DR_ / 2] : row[KVL_ + i - DR_ / 2];
        float v = x * cosT[s * DR_ + i] + rot * sinT[s * DR_ + i];
        __nv_bfloat16 h = __float2bfloat16(v);
        kfh[s * CF_ + KVL_ + i] = h;
        kfl[s * CF_ + KVL_ + i] = __float2bfloat16(v - __bfloat162float(h));
    }
}

// ---------------------------------------------------------------------------
// q_pe rope: read q hi/lo, write qf hi/lo cols 512..575. grid (S, H), 64 thr
// ---------------------------------------------------------------------------
__global__ void qrope_kernel(const __nv_bfloat16* __restrict__ qh,
                             const __nv_bfloat16* __restrict__ ql,
                             const float* __restrict__ cosT,
                             const float* __restrict__ sinT,
                             __nv_bfloat16* __restrict__ qfh,
                             __nv_bfloat16* __restrict__ qfl) {
    long s = blockIdx.x;
    int h = blockIdx.y;
    int i = threadIdx.x;
    long base = s * (long)(H_ * DF_) + h * DF_ + DN_;
    float x = __bfloat162float(qh[base + i]) + __bfloat162float(ql[base + i]);
    int j = (i < DR_ / 2) ? (i + DR_ / 2) : (i - DR_ / 2);
    float xr = __bfloat162float(qh[base + j]) + __bfloat162float(ql[base + j]);
    float rot = (i < DR_ / 2) ? -xr : xr;
    float v = x * cosT[s * DR_ + i] + rot * sinT[s * DR_ + i];
    long o = ((long)h * S_ + s) * CF_ + KVL_ + i;
    __nv_bfloat16 hh = __float2bfloat16(v);
    qfh[o] = hh;
    qfl[o] = __float2bfloat16(v - __bfloat162float(hh));
}

// ---------------------------------------------------------------------------
// causal softmax: scores fp32 -> attn hi/lo bf16; zero-fill only to the
// 128-row-tile boundary (olat never reads past it).
// ---------------------------------------------------------------------------
__global__ void softmax_causal_kernel(const float* __restrict__ scores,
                                      __nv_bfloat16* __restrict__ ah,
                                      __nv_bfloat16* __restrict__ al) {
    long s = blockIdx.x;
    int h = blockIdx.y;
    const float* row = scores + ((long)h * S_ + s) * S_;
    __nv_bfloat16* hrow = ah + ((long)h * S_ + s) * S_;
    __nv_bfloat16* lrow = al + ((long)h * S_ + s) * S_;
    int L = (int)s + 1;
    int Lpad = (((int)s >> 7) + 1) << 7;
    float v[8];
    int cnt = 0;
    float m = -3.4e38f;
    for (int i = threadIdx.x; i < L; i += 256) { v[cnt] = row[i]; m = fmaxf(m, v[cnt]); cnt++; }
    m = blockReduceMax(m);
    float sum = 0.f;
    for (int j = 0; j < cnt; j++) { v[j] = __expf(v[j] - m); sum += v[j]; }
    sum = blockReduceSum(sum);
    float inv = 1.f / sum;
    cnt = 0;
    for (int i = threadIdx.x; i < L; i += 256) {
        float p = v[cnt++] * inv;
        __nv_bfloat16 hh = __float2bfloat16(p);
        hrow[i] = hh;
        lrow[i] = __float2bfloat16(p - __bfloat162float(hh));
    }
    __nv_bfloat16 z = __float2bfloat16(0.f);
    for (int i = L + threadIdx.x; i < Lpad; i += 256) { hrow[i] = z; lrow[i] = z; }
}

// ---------------------------------------------------------------------------
// swiglu: gu fp32 -> act hi/lo
// ---------------------------------------------------------------------------
__global__ void swiglu_kernel(const float* __restrict__ gu,
                              __nv_bfloat16* __restrict__ ah,
                              __nv_bfloat16* __restrict__ al) {
    long idx = (long)blockIdx.x * blockDim.x + threadIdx.x;
    if (idx >= (long)S_ * I_) return;
    long s = idx / I_, i = idx % I_;
    float g = gu[s * (2L * I_) + i];
    float u = gu[s * (2L * I_) + I_ + i];
    float v = (g / (1.f + __expf(-g))) * u;
    __nv_bfloat16 h = __float2bfloat16(v);
    ah[idx] = h;
    al[idx] = __float2bfloat16(v - __bfloat162float(h));
}

// ---------------------------------------------------------------------------
// host orchestration
// ---------------------------------------------------------------------------
#define SMEM_T  (2 * (2 * TILE_A + 2 * TILE_BT))   // 75776
#define SMEM_NT (2 * (2 * TILE_A + 2 * TILE_BN))   // 81920

struct GArgs {
    const __nv_bfloat16 *Ah, *Al, *Bh, *Bl;
    int lda, ldb, ldc, M, N, K, batch, causal, ldad;
    long sA, sB, sC, sAd;
    float *Cf, alpha;
    __nv_bfloat16 *Chi, *Clo;
    const float* add;
};

static void launch_g(bool btrans, const GArgs& a) {
    dim3 grid(a.M / 128, (a.N + 127) / 128, a.batch);
    if (btrans)
        gemm_tc<1><<<grid, 128, SMEM_T>>>(a.Ah, a.Al, a.lda, a.sA, a.Bh, a.Bl, a.ldb, a.sB,
                                          a.Cf, a.Chi, a.Clo, a.ldc, a.sC,
                                          a.M, a.N, a.K, a.alpha, a.add, a.ldad, a.sAd, a.causal);
    else
        gemm_tc<0><<<grid, 128, SMEM_NT>>>(a.Ah, a.Al, a.lda, a.sA, a.Bh, a.Bl, a.ldb, a.sB,
                                           a.Cf, a.Chi, a.Clo, a.ldc, a.sC,
                                           a.M, a.N, a.K, a.alpha, a.add, a.ldad, a.sAd, a.causal);
}

extern "C" void kernel_launch(void* const* d_in, const int* in_sizes, int n_in,
                              void* d_out, int out_size) {
    const float* hidden    = (const float*)d_in[0];
    const float* cosT      = (const float*)d_in[1];
    const float* sinT      = (const float*)d_in[2];
    const float* ln1_w     = (const float*)d_in[3];
    const float* q_a_w     = (const float*)d_in[4];
    const float* q_a_ln_w  = (const float*)d_in[5];
    const float* q_b_w     = (const float*)d_in[6];
    const float* kv_a_w    = (const float*)d_in[7];
    const float* kv_a_ln_w = (const float*)d_in[8];
    const float* kc_w      = (const float*)d_in[9];
    const float* vc_w      = (const float*)d_in[10];
    const float* o_w       = (const float*)d_in[11];
    const float* ln2_w     = (const float*)d_in[12];
    const float* gate_up_w = (const float*)d_in[13];
    const float* down_w    = (const float*)d_in[14];
    float* out             = (float*)d_out;

    cudaFuncSetAttribute(gemm_tc<1>, cudaFuncAttributeMaxDynamicSharedMemorySize, SMEM_T);
    cudaFuncSetAttribute(gemm_tc<0>, cudaFuncAttributeMaxDynamicSharedMemorySize, SMEM_NT);

    float* sc = nullptr;
    cudaGetSymbolAddress((void**)&sc, g_scratch);
    __nv_bfloat16* bf = nullptr;
    cudaGetSymbolAddress((void**)&bf, g_bf);

    float* qkv    = sc + OFF_QKV;
    float* scores = sc + OFF_SCORES;
    float* hid2   = sc + OFF_HID2;
    float* gu     = sc + OFF_GU;

    auto HI = [&](long off) { return bf + off; };
    auto LO = [&](long off, long E) { return bf + off + E; };

    auto SPLIT = [&](const float* src, long off, long E) {
        long n4 = E / 4;
        split_rm<<<(unsigned)((n4 + 255) / 256), 256>>>(src, HI(off), LO(off, E), n4);
    };

    // --- weight splits (q_a_w and kv_a_w interleave into one [D][2112] B) ---
    {
        long n4a = ((long)D_ * QL_) / 4;
        split_stride<<<(unsigned)((n4a + 255) / 256), 256>>>(
            q_a_w, HI(B_WQKV), LO(B_WQKV, E_WQKV), QL_, NQKV_, 0, n4a);
        long n4b = ((long)D_ * CF_) / 4;
        split_stride<<<(unsigned)((n4b + 255) / 256), 256>>>(
            kv_a_w, HI(B_WQKV), LO(B_WQKV, E_WQKV), CF_, NQKV_, QL_, n4b);
    }
    SPLIT(q_b_w,     B_WQB,  E_WQB);
    SPLIT(kc_w,      B_WKC,  E_WKC);
    SPLIT(vc_w,      B_WVC,  E_WVC);
    SPLIT(o_w,       B_WO,   E_WO);
    SPLIT(gate_up_w, B_WGU,  E_WGU);
    SPLIT(down_w,    B_WDN,  E_WDN);

    // 1. h = rmsnorm(hidden) -> hi/lo
    rmsnorm_split_kernel<<<S_, 256>>>(hidden, D_, ln1_w, HI(B_HS), LO(B_HS, E_HS), D_);

    GArgs a{};

    // 2. qkv = h @ [q_a_w | kv_a_w]   (fused, fp32 out, N=2112)
    a = {HI(B_HS), LO(B_HS, E_HS), HI(B_WQKV), LO(B_WQKV, E_WQKV),
         D_, NQKV_, NQKV_, S_, NQKV_, D_, 1, 0, 0, 0, 0, 0, 0,
         qkv, 1.f, nullptr, nullptr, nullptr};
    launch_g(true, a);

    // 3. qas = rmsnorm(qkv[:, :1536]) -> hi/lo
    rmsnorm_split_kernel<<<S_, 256>>>(qkv, NQKV_, q_a_ln_w, HI(B_QAS), LO(B_QAS, E_QAS), QL_);

    // 4. q = qas @ q_b_w -> hi/lo
    a = {HI(B_QAS), LO(B_QAS, E_QAS), HI(B_WQB), LO(B_WQB, E_WQB),
         QL_, H_ * DF_, H_ * DF_, S_, H_ * DF_, QL_, 1, 0, 0, 0, 0, 0, 0,
         nullptr, 1.f, HI(B_QS), LO(B_QS, E_QS), nullptr};
    launch_g(true, a);

    // 5. kf = [rmsnorm(qkv[:, 1536:2048]), rope(qkv[:, 2048:2112])] -> hi/lo
    kprep_kernel<<<S_, 256>>>(qkv, kv_a_ln_w, cosT, sinT, HI(B_KFS), LO(B_KFS, E_KFS));

    // 6. qf[:, :512] = q_nope @ kc_w per head -> hi/lo
    a = {HI(B_QS), LO(B_QS, E_QS), HI(B_WKC), LO(B_WKC, E_WKC),
         H_ * DF_, KVL_, CF_, S_, KVL_, DN_, H_, 0, 0,
         (long)DF_, (long)DN_ * KVL_, (long)S_ * CF_, 0,
         nullptr, 1.f, HI(B_QFS), LO(B_QFS, E_QFS), nullptr};
    launch_g(true, a);

    // 7. qf[:, 512:576] = rope(q_pe) -> hi/lo
    qrope_kernel<<<dim3(S_, H_), DR_>>>(HI(B_QS), LO(B_QS, E_QS), cosT, sinT,
                                        HI(B_QFS), LO(B_QFS, E_QFS));

    // 8. scores = SCALE * qf @ kf^T  (causal block skip)
    a = {HI(B_QFS), LO(B_QFS, E_QFS), HI(B_KFS), LO(B_KFS, E_KFS),
         CF_, CF_, S_, S_, S_, CF_, H_, 1, 0,
         (long)S_ * CF_, 0, (long)S_ * S_, 0,
         scores, SCALE_, nullptr, nullptr, nullptr};
    launch_g(false, a);

    // 9. softmax -> attn hi/lo (trimmed zero fill)
    softmax_causal_kernel<<<dim3(S_, H_), 256>>>(scores, HI(B_ATT), LO(B_ATT, E_ATT));

    // 10. olat = attn @ k_lat  (B trans [k=t][n=c], K causal-limited)
    a = {HI(B_ATT), LO(B_ATT, E_ATT), HI(B_KFS), LO(B_KFS, E_KFS),
         S_, CF_, KVL_, S_, KVL_, S_, H_, 2, 0,
         (long)S_ * S_, 0, (long)S_ * KVL_, 0,
         nullptr, 1.f, HI(B_OLS), LO(B_OLS, E_OLS), nullptr};
    launch_g(true, a);

    // 11. o[:, h*128:] = olat @ vc_w per head -> hi/lo
    a = {HI(B_OLS), LO(B_OLS, E_OLS), HI(B_WVC), LO(B_WVC, E_WVC),
         KVL_, DV_, H_ * DV_, S_, DV_, KVL_, H_, 0, 0,
         (long)S_ * KVL_, (long)KVL_ * DV_, (long)DV_, 0,
         nullptr, 1.f, HI(B_OS), LO(B_OS, E_OS), nullptr};
    launch_g(true, a);

    // 12. hid2 = o @ o_w + hidden  (fp32)
    a = {HI(B_OS), LO(B_OS, E_OS), HI(B_WO), LO(B_WO, E_WO),
         H_ * DV_, D_, D_, S_, D_, H_ * DV_, 1, 0, D_, 0, 0, 0, 0,
         hid2, 1.f, nullptr, nullptr, hidden};
    launch_g(true, a);

    // 13. x2 = rmsnorm(hid2) -> hi/lo
    rmsnorm_split_kernel<<<S_, 256>>>(hid2, D_, ln2_w, HI(B_X2S), LO(B_X2S, E_X2S), D_);

    // 14. gu = x2 @ gate_up_w  (fp32)
    a = {HI(B_X2S), LO(B_X2S, E_X2S), HI(B_WGU), LO(B_WGU, E_WGU),
         D_, 2 * I_, 2 * I_, S_, 2 * I_, D_, 1, 0, 0, 0, 0, 0, 0,
         gu, 1.f, nullptr, nullptr, nullptr};
    launch_g(true, a);

    // 15. act = swiglu(gu) -> hi/lo
    {
        long total = (long)S_ * I_;
        swiglu_kernel<<<(unsigned)((total + 255) / 256), 256>>>(gu, HI(B_ACTS), LO(B_ACTS, E_ACTS));
    }

    // 16. out = act @ down_w + hid2  (fp32)
    a = {HI(B_ACTS), LO(B_ACTS, E_ACTS), HI(B_WDN), LO(B_WDN, E_WDN),
         I_, D_, D_, S_, D_, I_, 1, 0, D_, 0, 0, 0, 0,
         out, 1.f, nullptr, nullptr, hid2};
    launch_g(true, a);
}